// round 7
// baseline (speedup 1.0000x reference)
#include <cuda_runtime.h>
#include <cuda_bf16.h>
#include <cstdint>

#define BATCH 8
#define CDIM  64
#define NPTS  4096
#define KNBR  16
#define COUT  64
#define KSUP  32          // approximate superset size per row
#define NC    128         // candidates per tile in phase B
#define NTIL  (NPTS / NC) // 32
#define KINIT 0xFF7FFFFFu // fsort(FLT_MAX)

typedef unsigned long long ull;

// ---------------- scratch (no allocations allowed) ----------------
__device__ float          g_sq  [BATCH * NPTS];
__device__ int            g_idx [BATCH * NPTS * KNBR];
__device__ float          g_A   [BATCH * NPTS * COUT];
__device__ float          g_Cp  [BATCH * NPTS * COUT];
__device__ float          g_xt  [BATCH * NPTS * CDIM];   // point-major fp32
__device__ __nv_bfloat16  g_xh  [BATCH * NPTS * CDIM];   // point-major bf16
__device__ short          g_cand[BATCH * NPTS * KSUP];

// ---------------- helpers ----------------
__device__ __forceinline__ uint32_t smem_u32(const void* p) {
    uint32_t a;
    asm("{ .reg .u64 t; cvta.to.shared.u64 t, %1; cvt.u32.u64 %0, t; }" : "=r"(a) : "l"(p));
    return a;
}
__device__ __forceinline__ unsigned fsort(float v) {
    unsigned u = __float_as_uint(v);
    return u ^ (0x80000000u | (unsigned)((int)u >> 31));
}
__device__ __forceinline__ float funsort(unsigned s) {
    unsigned u = (s & 0x80000000u) ? (s ^ 0x80000000u) : ~s;
    return __uint_as_float(u);
}
__device__ __forceinline__ void ldmx4(uint32_t* r, uint32_t addr) {
    asm volatile("ldmatrix.sync.aligned.m8n8.x4.shared.b16 {%0,%1,%2,%3}, [%4];"
                 : "=r"(r[0]), "=r"(r[1]), "=r"(r[2]), "=r"(r[3]) : "r"(addr));
}
__device__ __forceinline__ void mma16816(float* c, const uint32_t* a, uint32_t b0, uint32_t b1) {
    asm volatile("mma.sync.aligned.m16n8k16.row.col.f32.bf16.bf16.f32 "
                 "{%0,%1,%2,%3}, {%4,%5,%6,%7}, {%8,%9}, {%0,%1,%2,%3};"
                 : "+f"(c[0]), "+f"(c[1]), "+f"(c[2]), "+f"(c[3])
                 : "r"(a[0]), "r"(a[1]), "r"(a[2]), "r"(a[3]), "r"(b0), "r"(b1));
}
// swizzled byte offset of 16B granule g (0..7) in row rr of a [rows][64bf16] tile
__device__ __forceinline__ int swz(int rr, int g) {
    return rr * 128 + ((g ^ (rr & 7)) << 4);
}

// ---------------- kernel 1: squared norms (exact fp32) ----------------
__global__ void sq_kernel(const float* __restrict__ x) {
    int b = blockIdx.y;
    int n = blockIdx.x * blockDim.x + threadIdx.x;
    const float* xp = x + (size_t)b * CDIM * NPTS + n;
    float s = 0.f;
#pragma unroll
    for (int c = 0; c < CDIM; ++c) { float v = xp[c * NPTS]; s = fmaf(v, v, s); }
    g_sq[b * NPTS + n] = s;
}

// ---------------- kernel 1b: transpose to point-major fp32 + bf16 ----------------
__global__ void tr_kernel(const float* __restrict__ x) {
    __shared__ float tile[32][33];
    const int tx = threadIdx.x, ty = threadIdx.y;
    const int n0 = blockIdx.x * 32, c0 = blockIdx.y * 32, b = blockIdx.z;
    const float* xb = x + (size_t)b * CDIM * NPTS;
#pragma unroll
    for (int i = 0; i < 4; ++i)
        tile[ty + i * 8][tx] = xb[(c0 + ty + i * 8) * NPTS + n0 + tx];
    __syncthreads();
#pragma unroll
    for (int i = 0; i < 4; ++i) {
        int n = n0 + ty + i * 8, c = c0 + tx;
        float v = tile[tx][ty + i * 8];
        size_t o = ((size_t)b * NPTS + n) * CDIM + c;
        g_xt[o] = v;
        g_xh[o] = __float2bfloat16(v);
    }
}

// ---------------- kernel 2: HMMA approx distances + top-32 superset ----------------
#define PAD     132
#define SM_A    0                          // 16384
#define SM_B0   16384                      // 16384
#define SM_B1   32768                      // 16384
#define SM_SQSL 49152                      // float[2][128] = 1024
#define SM_VB   (SM_SQSL + 1024)           // float[128*132] = 67584
#define KNN_SMEM (SM_VB + 128 * PAD * 4)

__global__ __launch_bounds__(256) void knn_mma_kernel() {
    extern __shared__ char sm[];
    float* sqsl = (float*)(sm + SM_SQSL);
    float* vb   = (float*)(sm + SM_VB);

    const int tid  = threadIdx.x;
    const int w    = tid >> 5;
    const int lane = tid & 31;
    const int b    = blockIdx.y;
    const int row0 = blockIdx.x * 128;
    const uint32_t smb = smem_u32(sm);

    const __nv_bfloat16* gb = g_xh + (size_t)b * NPTS * CDIM;

    // prologue: A tile (swizzled), B tile 0, sq slice 0
#pragma unroll
    for (int i = 0; i < 4; ++i) {
        int q = tid + i * 256, rr = q >> 3, g = q & 7;
        *(uint4*)(sm + SM_A + swz(rr, g))  = *(const uint4*)(gb + (size_t)(row0 + rr) * CDIM + g * 8);
        *(uint4*)(sm + SM_B0 + swz(rr, g)) = *(const uint4*)(gb + (size_t)rr * CDIM + g * 8);
    }
    if (tid < 32)
        *(float4*)(sqsl + tid * 4) = *(const float4*)(g_sq + (size_t)b * NPTS + tid * 4);
    __syncthreads();

    // GEMM role (all 8 warps): rows wrow..wrow+15
    const int wrow = w * 16;
    const int arow = wrow + (lane & 7) + ((lane >> 3) & 1) * 8;
    const int rA   = wrow + (lane >> 2);
    const int rB   = rA + 8;
    const int mloc = (lane & 3) * 2;

    // A fragments: block-constant, load once
    uint32_t af[4][4];
#pragma unroll
    for (int kc = 0; kc < 4; ++kc) {
        int ach = kc * 2 + (lane >> 4);
        ldmx4(af[kc], smb + SM_A + swz(arow, ach));
    }

    // selection state (threads 0..127 own row = row0 + tid), all thread-local
    unsigned kv[KSUP], ki[KSUP];
    unsigned worst = KINIT; int wpos = 0;
    float thrf = 3.4e38f;
#pragma unroll
    for (int s = 0; s < KSUP; ++s) { kv[s] = KINIT; ki[s] = 0xFFFFu; }

    for (int t = 0; t < NTIL; ++t) {
        const uint32_t bbase = smb + ((t & 1) ? SM_B1 : SM_B0);
        const float*   sql   = sqsl + (t & 1) * 128;

#pragma unroll
        for (int nf = 0; nf < 16; ++nf) {
            int brow = nf * 8 + (lane & 7);
            int bg   = lane >> 3;
            uint32_t p[4], q4[4];
            ldmx4(p,  bbase + swz(brow, bg));
            ldmx4(q4, bbase + swz(brow, bg + 4));
            float acc[4] = {0.f, 0.f, 0.f, 0.f};
            mma16816(acc, af[0], p[0],  p[1]);
            mma16816(acc, af[1], p[2],  p[3]);
            mma16816(acc, af[2], q4[0], q4[1]);
            mma16816(acc, af[3], q4[2], q4[3]);

            // branch-free epilogue: v = sq[m] - 2*dot -> vbuf
            int   ml = mloc + nf * 8;
            float s0 = sql[ml], s1 = sql[ml + 1];
            *(float2*)(vb + rA * PAD + ml) =
                make_float2(fmaf(-2.f, acc[0], s0), fmaf(-2.f, acc[1], s1));
            *(float2*)(vb + rB * PAD + ml) =
                make_float2(fmaf(-2.f, acc[2], s0), fmaf(-2.f, acc[3], s1));
        }
        __syncthreads();   // vbuf complete

        if (tid < 128) {
            // thread-local scan of own row; threshold tightens within the scan
            const float* vr = vb + tid * PAD;
            const int    tb = t * NC;
#define INS(vv, mm) do {                                              \
    kv[wpos] = fsort(vv); ki[wpos] = (unsigned)(mm);                  \
    unsigned wv_ = kv[0]; int pp_ = 0;                                \
    _Pragma("unroll")                                                 \
    for (int s_ = 1; s_ < KSUP; ++s_)                                 \
        if (kv[s_] > wv_) { wv_ = kv[s_]; pp_ = s_; }                 \
    worst = wv_; wpos = pp_; thrf = funsort(worst);                   \
} while (0)
#pragma unroll 4
            for (int jj = 0; jj < NC; jj += 4) {
                float4 v4 = *(const float4*)(vr + jj);
                if (v4.x <= thrf) INS(v4.x, tb + jj);
                if (v4.y <= thrf) INS(v4.y, tb + jj + 1);
                if (v4.z <= thrf) INS(v4.z, tb + jj + 2);
                if (v4.w <= thrf) INS(v4.w, tb + jj + 3);
            }
#undef INS
        } else if (t + 1 < NTIL) {
            // warps 4-7: prefetch next B tile + sq slice
            char* dst = sm + (((t + 1) & 1) ? SM_B1 : SM_B0);
            const __nv_bfloat16* src = gb + (size_t)(t + 1) * NC * CDIM;
            int t2 = tid - 128;
#pragma unroll
            for (int i = 0; i < 8; ++i) {
                int q = t2 + i * 128, rr = q >> 3, g = q & 7;
                *(uint4*)(dst + swz(rr, g)) = *(const uint4*)(src + (size_t)rr * CDIM + g * 8);
            }
            if (t2 < 32)
                *(float4*)(sqsl + ((t + 1) & 1) * 128 + t2 * 4) =
                    *(const float4*)(g_sq + (size_t)b * NPTS + (t + 1) * NC + t2 * 4);
        }
        __syncthreads();   // vbuf reusable; B(t+1) ready
    }

    if (tid < 128) {
        short* op = g_cand + ((size_t)b * NPTS + row0 + tid) * KSUP;
#pragma unroll
        for (int k = 0; k < KSUP; ++k) op[k] = (short)ki[k];
    }
}

// ---------------- kernel 2b: exact rescore (coalesced), top-16 ----------------
__global__ __launch_bounds__(256) void rescore_kernel() {
    __shared__ float xrow[8][CDIM];
    __shared__ float dots[8][KSUP];
    const int lane = threadIdx.x & 31;
    const int w    = threadIdx.x >> 5;
    const int b    = blockIdx.y;
    const int n    = blockIdx.x * 8 + w;
    const size_t rb = (size_t)b * NPTS + n;

    // stage own row
    *(float2*)(&xrow[w][lane * 2]) = *(const float2*)(g_xt + rb * CDIM + lane * 2);
    __syncwarp();

    const short* cp = g_cand + rb * KSUP;
    const float* xseg = &xrow[w][(lane & 3) * 16];

    // 4 groups of 8 candidates; 4 lanes per candidate (coalesced 256B rows)
#pragma unroll
    for (int g = 0; g < 4; ++g) {
        int c = g * 8 + (lane >> 2);
        int j = (int)cp[c];
        const float* yp = g_xt + ((size_t)b * NPTS + j) * CDIM + (lane & 3) * 16;
        float d = 0.f;
#pragma unroll
        for (int q = 0; q < 4; ++q) {
            float4 yv = *(const float4*)(yp + q * 4);
            float4 xv = *(const float4*)(xseg + q * 4);
            d = fmaf(xv.x, yv.x, d);
            d = fmaf(xv.y, yv.y, d);
            d = fmaf(xv.z, yv.z, d);
            d = fmaf(xv.w, yv.w, d);
        }
        d += __shfl_xor_sync(0xffffffffu, d, 1);
        d += __shfl_xor_sync(0xffffffffu, d, 2);
        if ((lane & 3) == 0) dots[w][c] = d;
    }
    __syncwarp();

    int j = (int)cp[lane];
    ull key;
    if (j == n) {
        key = ~0ULL;
    } else {
        float dist = fmaf(-2.f, dots[w][lane], g_sq[(size_t)b * NPTS + j]);
        key = ((ull)fsort(dist) << 32) | (unsigned)j;
    }
    // 32-lane bitonic sort (ascending)
#pragma unroll
    for (int k = 2; k <= 32; k <<= 1) {
#pragma unroll
        for (int jj = k >> 1; jj > 0; jj >>= 1) {
            ull other = __shfl_xor_sync(0xffffffffu, key, jj);
            bool up   = ((lane & k) == 0);
            bool low  = ((lane & jj) == 0);
            bool keep_small = (low == up);
            ull mn = key < other ? key : other;
            ull mx = key < other ? other : key;
            key = keep_small ? mn : mx;
        }
    }
    if (lane < KNBR)
        g_idx[rb * KNBR + lane] = (int)(key & 0xFFFFu);
}

// ---------------- kernel 3: A = W1.x ; Cpre = (W2-W1).x + b1+b2 ----------------
__global__ void feat_kernel(const float* __restrict__ x,
                            const float* __restrict__ W1, const float* __restrict__ b1,
                            const float* __restrict__ W2, const float* __restrict__ b2) {
    __shared__ float xs [CDIM][64];
    __shared__ float w1s[COUT][CDIM];
    __shared__ float wds[COUT][CDIM];
    __shared__ float bs [COUT];

    const int tid = threadIdx.x;
    const int b   = blockIdx.y;
    const int n0  = blockIdx.x * 64;
    const float* xb = x + (size_t)b * CDIM * NPTS;

#pragma unroll
    for (int i = 0; i < 4; ++i) {
        int q = tid + i * 256, c = q >> 4, mg = q & 15;
        *(float4*)(&xs[c][mg * 4]) = *(const float4*)(xb + c * NPTS + n0 + mg * 4);
    }
#pragma unroll
    for (int i = 0; i < 4; ++i) {
        int q = tid + i * 256, o = q >> 4, cg = (q & 15) * 4;
        float4 w1v = *(const float4*)(W1 + o * CDIM + cg);
        float4 w2v = *(const float4*)(W2 + o * CDIM + cg);
        *(float4*)(&w1s[o][cg]) = w1v;
        *(float4*)(&wds[o][cg]) = make_float4(w2v.x - w1v.x, w2v.y - w1v.y,
                                              w2v.z - w1v.z, w2v.w - w1v.w);
    }
    if (tid < COUT) bs[tid] = b1[tid] + b2[tid];
    __syncthreads();

    const int tx = tid & 15;
    const int ty = tid >> 4;
    float aA[4][4] = {}, aC[4][4] = {};
#pragma unroll 16
    for (int c = 0; c < CDIM; ++c) {
        float4 xv = *(const float4*)(&xs[c][tx * 4]);
        float xr[4] = { xv.x, xv.y, xv.z, xv.w };
#pragma unroll
        for (int jj = 0; jj < 4; ++jj) {
            float w1e = w1s[ty * 4 + jj][c];
            float wde = wds[ty * 4 + jj][c];
#pragma unroll
            for (int i = 0; i < 4; ++i) {
                aA[i][jj] = fmaf(xr[i], w1e, aA[i][jj]);
                aC[i][jj] = fmaf(xr[i], wde, aC[i][jj]);
            }
        }
    }
#pragma unroll
    for (int i = 0; i < 4; ++i) {
        int n = n0 + tx * 4 + i;
        float* ap = g_A  + ((size_t)b * NPTS + n) * COUT + ty * 4;
        float* cp = g_Cp + ((size_t)b * NPTS + n) * COUT + ty * 4;
        *(float4*)ap = make_float4(aA[i][0], aA[i][1], aA[i][2], aA[i][3]);
        *(float4*)cp = make_float4(aC[i][0] + bs[ty * 4 + 0],
                                   aC[i][1] + bs[ty * 4 + 1],
                                   aC[i][2] + bs[ty * 4 + 2],
                                   aC[i][3] + bs[ty * 4 + 3]);
    }
}

// ---------------- kernel 4: gather-max + relu (2 points/thread ILP) ----------------
__global__ __launch_bounds__(256) void gather_kernel(float* __restrict__ out) {
    const int tid = threadIdx.x;
    const int b   = blockIdx.y;
    const int l   = tid & 63;
    const int g   = tid >> 6;
    const int n1  = blockIdx.x * 128 + l;
    const int n2  = n1 + 64;
    const int* ip1 = g_idx + ((size_t)b * NPTS + n1) * KNBR;
    const int* ip2 = g_idx + ((size_t)b * NPTS + n2) * KNBR;

    float mx1[16], mx2[16];
#pragma unroll
    for (int i = 0; i < 16; ++i) { mx1[i] = -3.4e38f; mx2[i] = -3.4e38f; }

#pragma unroll
    for (int k = 0; k < KNBR; ++k) {
        int j1 = ip1[k], j2 = ip2[k];
        const float4* ap1 = (const float4*)(g_A + ((size_t)b * NPTS + j1) * COUT + g * 16);
        const float4* ap2 = (const float4*)(g_A + ((size_t)b * NPTS + j2) * COUT + g * 16);
#pragma unroll
        for (int q = 0; q < 4; ++q) {
            float4 v1 = ap1[q];
            float4 v2 = ap2[q];
            mx1[q * 4 + 0] = fmaxf(mx1[q * 4 + 0], v1.x);
            mx1[q * 4 + 1] = fmaxf(mx1[q * 4 + 1], v1.y);
            mx1[q * 4 + 2] = fmaxf(mx1[q * 4 + 2], v1.z);
            mx1[q * 4 + 3] = fmaxf(mx1[q * 4 + 3], v1.w);
            mx2[q * 4 + 0] = fmaxf(mx2[q * 4 + 0], v2.x);
            mx2[q * 4 + 1] = fmaxf(mx2[q * 4 + 1], v2.y);
            mx2[q * 4 + 2] = fmaxf(mx2[q * 4 + 2], v2.z);
            mx2[q * 4 + 3] = fmaxf(mx2[q * 4 + 3], v2.w);
        }
    }
    const float4* cp1 = (const float4*)(g_Cp + ((size_t)b * NPTS + n1) * COUT + g * 16);
    const float4* cp2 = (const float4*)(g_Cp + ((size_t)b * NPTS + n2) * COUT + g * 16);
    float* op1 = out + ((size_t)b * COUT + g * 16) * NPTS + n1;
    float* op2 = out + ((size_t)b * COUT + g * 16) * NPTS + n2;
#pragma unroll
    for (int q = 0; q < 4; ++q) {
        float4 c1 = cp1[q];
        float4 c2 = cp2[q];
        op1[(q * 4 + 0) * NPTS] = fmaxf(c1.x + mx1[q * 4 + 0], 0.f);
        op1[(q * 4 + 1) * NPTS] = fmaxf(c1.y + mx1[q * 4 + 1], 0.f);
        op1[(q * 4 + 2) * NPTS] = fmaxf(c1.z + mx1[q * 4 + 2], 0.f);
        op1[(q * 4 + 3) * NPTS] = fmaxf(c1.w + mx1[q * 4 + 3], 0.f);
        op2[(q * 4 + 0) * NPTS] = fmaxf(c2.x + mx2[q * 4 + 0], 0.f);
        op2[(q * 4 + 1) * NPTS] = fmaxf(c2.y + mx2[q * 4 + 1], 0.f);
        op2[(q * 4 + 2) * NPTS] = fmaxf(c2.z + mx2[q * 4 + 2], 0.f);
        op2[(q * 4 + 3) * NPTS] = fmaxf(c2.w + mx2[q * 4 + 3], 0.f);
    }
}

// ---------------- launch ----------------
extern "C" void kernel_launch(void* const* d_in, const int* in_sizes, int n_in,
                              void* d_out, int out_size) {
    const float *x = nullptr, *W1 = nullptr, *b1 = nullptr, *W2 = nullptr, *b2 = nullptr;
    for (int i = 0; i < n_in; ++i) {
        int s = in_sizes[i];
        const float* p = (const float*)d_in[i];
        if      (s == BATCH * CDIM * NPTS) x = p;
        else if (s == COUT * CDIM)        { if (!W1) W1 = p; else W2 = p; }
        else if (s == COUT)               { if (!b1) b1 = p; else b2 = p; }
    }
    float* out = (float*)d_out;
    (void)out_size;

    cudaFuncSetAttribute(knn_mma_kernel, cudaFuncAttributeMaxDynamicSharedMemorySize, KNN_SMEM);

    sq_kernel      <<<dim3(NPTS / 256, BATCH), 256>>>(x);
    tr_kernel      <<<dim3(NPTS / 32, CDIM / 32, BATCH), dim3(32, 8)>>>(x);
    knn_mma_kernel <<<dim3(NPTS / 128, BATCH), 256, KNN_SMEM>>>();
    rescore_kernel <<<dim3(NPTS / 8, BATCH), 256>>>();
    feat_kernel    <<<dim3(NPTS / 64, BATCH), 256>>>(x, W1, b1, W2, b2);
    gather_kernel  <<<dim3(NPTS / 128, BATCH), 256>>>(out);
}

// round 8
// speedup vs baseline: 1.6600x; 1.6600x over previous
#include <cuda_runtime.h>
#include <cuda_bf16.h>
#include <cstdint>

#define BATCH 8
#define CDIM  64
#define NPTS  4096
#define KNBR  16
#define COUT  64
#define KSUP  32          // approximate superset size per row
#define NC    128         // candidates per tile in phase B
#define NTIL  (NPTS / NC) // 32
#define KINIT 0xFF7FFFFFu // fsort(FLT_MAX)

typedef unsigned long long ull;

// ---------------- scratch (no allocations allowed) ----------------
__device__ float          g_sq  [BATCH * NPTS];
__device__ int            g_idx [BATCH * NPTS * KNBR];
__device__ float          g_A   [BATCH * NPTS * COUT];
__device__ float          g_Cp  [BATCH * NPTS * COUT];
__device__ float          g_xt  [BATCH * NPTS * CDIM];   // point-major fp32
__device__ __nv_bfloat16  g_xh  [BATCH * NPTS * CDIM];   // point-major bf16
__device__ short          g_cand[BATCH * NPTS * KSUP];

// ---------------- helpers ----------------
__device__ __forceinline__ uint32_t smem_u32(const void* p) {
    uint32_t a;
    asm("{ .reg .u64 t; cvta.to.shared.u64 t, %1; cvt.u32.u64 %0, t; }" : "=r"(a) : "l"(p));
    return a;
}
__device__ __forceinline__ unsigned fsort(float v) {
    unsigned u = __float_as_uint(v);
    return u ^ (0x80000000u | (unsigned)((int)u >> 31));
}
__device__ __forceinline__ float funsort(unsigned s) {
    unsigned u = (s & 0x80000000u) ? (s ^ 0x80000000u) : ~s;
    return __uint_as_float(u);
}
__device__ __forceinline__ void ldmx4(uint32_t* r, uint32_t addr) {
    asm volatile("ldmatrix.sync.aligned.m8n8.x4.shared.b16 {%0,%1,%2,%3}, [%4];"
                 : "=r"(r[0]), "=r"(r[1]), "=r"(r[2]), "=r"(r[3]) : "r"(addr));
}
__device__ __forceinline__ void mma16816(float* c, const uint32_t* a, uint32_t b0, uint32_t b1) {
    asm volatile("mma.sync.aligned.m16n8k16.row.col.f32.bf16.bf16.f32 "
                 "{%0,%1,%2,%3}, {%4,%5,%6,%7}, {%8,%9}, {%0,%1,%2,%3};"
                 : "+f"(c[0]), "+f"(c[1]), "+f"(c[2]), "+f"(c[3])
                 : "r"(a[0]), "r"(a[1]), "r"(a[2]), "r"(a[3]), "r"(b0), "r"(b1));
}
// swizzled byte offset of 16B granule g (0..7) in row rr of a [rows][64bf16] tile
__device__ __forceinline__ int swz(int rr, int g) {
    return rr * 128 + ((g ^ (rr & 7)) << 4);
}

// ---------------- kernel 1: squared norms (exact fp32) ----------------
__global__ void sq_kernel(const float* __restrict__ x) {
    int b = blockIdx.y;
    int n = blockIdx.x * blockDim.x + threadIdx.x;
    const float* xp = x + (size_t)b * CDIM * NPTS + n;
    float s = 0.f;
#pragma unroll
    for (int c = 0; c < CDIM; ++c) { float v = xp[c * NPTS]; s = fmaf(v, v, s); }
    g_sq[b * NPTS + n] = s;
}

// ---------------- kernel 1b: transpose to point-major fp32 + bf16 ----------------
__global__ void tr_kernel(const float* __restrict__ x) {
    __shared__ float tile[32][33];
    const int tx = threadIdx.x, ty = threadIdx.y;
    const int n0 = blockIdx.x * 32, c0 = blockIdx.y * 32, b = blockIdx.z;
    const float* xb = x + (size_t)b * CDIM * NPTS;
#pragma unroll
    for (int i = 0; i < 4; ++i)
        tile[ty + i * 8][tx] = xb[(c0 + ty + i * 8) * NPTS + n0 + tx];
    __syncthreads();
#pragma unroll
    for (int i = 0; i < 4; ++i) {
        int n = n0 + ty + i * 8, c = c0 + tx;
        float v = tile[tx][ty + i * 8];
        size_t o = ((size_t)b * NPTS + n) * CDIM + c;
        g_xt[o] = v;
        g_xh[o] = __float2bfloat16(v);
    }
}

// ---------------- kernel 2: HMMA approx distances + top-32 superset ----------------
// pend: [128 rows][4 quad-lane segments][32 entries] ull; register-local counters,
// zero atomics, capacity exactly matches the 32 values a lane produces per row/tile.
#define SM_A    0                           // 16384
#define SM_B0   16384                       // 16384
#define SM_B1   32768                       // 16384
#define SM_SQSL 49152                       // float[2][128] = 1024
#define SM_THR  (SM_SQSL + 1024)            // float[128]    = 512
#define SM_CNT4 (SM_THR + 512)              // int[128][4]   = 2048
#define SM_PEND (SM_CNT4 + 2048)            // ull[128*4*32] = 131072
#define KNN_SMEM (SM_PEND + 131072)

__global__ __launch_bounds__(256) void knn_mma_kernel() {
    extern __shared__ char sm[];
    float* sqsl = (float*)(sm + SM_SQSL);
    float* thr  = (float*)(sm + SM_THR);
    int*   cnt4 = (int*)  (sm + SM_CNT4);
    ull*   pend = (ull*)  (sm + SM_PEND);

    const int tid  = threadIdx.x;
    const int w    = tid >> 5;
    const int lane = tid & 31;
    const int b    = blockIdx.y;
    const int row0 = blockIdx.x * 128;
    const uint32_t smb = smem_u32(sm);

    const __nv_bfloat16* gb = g_xh + (size_t)b * NPTS * CDIM;

    // prologue: A tile (swizzled), B tile 0, sq slice 0, thr
#pragma unroll
    for (int i = 0; i < 4; ++i) {
        int q = tid + i * 256, rr = q >> 3, g = q & 7;
        *(uint4*)(sm + SM_A + swz(rr, g))  = *(const uint4*)(gb + (size_t)(row0 + rr) * CDIM + g * 8);
        *(uint4*)(sm + SM_B0 + swz(rr, g)) = *(const uint4*)(gb + (size_t)rr * CDIM + g * 8);
    }
    if (tid < 32)
        *(float4*)(sqsl + tid * 4) = *(const float4*)(g_sq + (size_t)b * NPTS + tid * 4);
    if (tid < 128) thr[tid] = 3.4e38f;
    __syncthreads();

    // GEMM role (all 8 warps): rows wrow..wrow+15
    const int wrow = w * 16;
    const int arow = wrow + (lane & 7) + ((lane >> 3) & 1) * 8;
    const int rA   = wrow + (lane >> 2);
    const int rB   = rA + 8;
    const int seg  = lane & 3;
    const int mloc = seg * 2;
    ull* pendA = pend + (rA * 4 + seg) * 32;
    ull* pendB = pend + (rB * 4 + seg) * 32;

    // A fragments: block-constant, load once
    uint32_t af[4][4];
#pragma unroll
    for (int kc = 0; kc < 4; ++kc) {
        int ach = kc * 2 + (lane >> 4);
        ldmx4(af[kc], smb + SM_A + swz(arow, ach));
    }

    // selection state (threads 0..127 own row = row0 + tid), 32-bit split keys
    unsigned kv[KSUP], ki[KSUP];
    unsigned worst = KINIT; int wpos = 0;
#pragma unroll
    for (int s = 0; s < KSUP; ++s) { kv[s] = KINIT; ki[s] = 0xFFFFu; }

    for (int t = 0; t < NTIL; ++t) {
        const uint32_t bbase = smb + ((t & 1) ? SM_B1 : SM_B0);
        const float*   sql   = sqsl + (t & 1) * 128;
        const float thrA = thr[rA];
        const float thrB = thr[rB];
        const int   tb   = t * NC;
        int cA = 0, cB = 0;   // register-local append counters (<=32 by construction)

#pragma unroll
        for (int nf = 0; nf < 16; ++nf) {
            int brow = nf * 8 + (lane & 7);
            int bg   = lane >> 3;
            uint32_t p[4], q4[4];
            ldmx4(p,  bbase + swz(brow, bg));
            ldmx4(q4, bbase + swz(brow, bg + 4));
            float acc[4] = {0.f, 0.f, 0.f, 0.f};
            mma16816(acc, af[0], p[0],  p[1]);
            mma16816(acc, af[1], p[2],  p[3]);
            mma16816(acc, af[2], q4[0], q4[1]);
            mma16816(acc, af[3], q4[2], q4[3]);

            // fused epilogue: atomic-free threshold/append
            int   ml = mloc + nf * 8;
            float s0 = sql[ml], s1 = sql[ml + 1];
            int   m0 = tb + ml;
            float v00 = fmaf(-2.f, acc[0], s0);
            float v01 = fmaf(-2.f, acc[1], s1);
            float v10 = fmaf(-2.f, acc[2], s0);
            float v11 = fmaf(-2.f, acc[3], s1);
            if (v00 <= thrA) { pendA[cA++] = ((ull)fsort(v00) << 32) | (unsigned)m0; }
            if (v01 <= thrA) { pendA[cA++] = ((ull)fsort(v01) << 32) | (unsigned)(m0 + 1); }
            if (v10 <= thrB) { pendB[cB++] = ((ull)fsort(v10) << 32) | (unsigned)m0; }
            if (v11 <= thrB) { pendB[cB++] = ((ull)fsort(v11) << 32) | (unsigned)(m0 + 1); }
        }
        cnt4[rA * 4 + seg] = cA;
        cnt4[rB * 4 + seg] = cB;
        __syncthreads();   // appends + counts visible

        if (tid < 128) {
            // coherent flush: thread tid owns row tid; 4 segments
#pragma unroll
            for (int sg = 0; sg < 4; ++sg) {
                unsigned myc  = (unsigned)cnt4[tid * 4 + sg];
                unsigned cmax = __reduce_max_sync(0xffffffffu, myc);
                const ull* ps = pend + (tid * 4 + sg) * 32;
                for (unsigned j = 0; j < cmax; ++j) {
                    unsigned kvn = 0xFFFFFFFFu, kin = 0;
                    if (j < myc) {
                        ull e = ps[j];
                        kvn = (unsigned)(e >> 32);
                        kin = (unsigned)e;
                    }
                    bool take = kvn < worst;
                    if (__any_sync(0xffffffffu, take)) {
#pragma unroll
                        for (int s = 0; s < KSUP; ++s)
                            if (take && s == wpos) { kv[s] = kvn; ki[s] = kin; }
                        unsigned wv = kv[0]; int pp = 0;
#pragma unroll
                        for (int s = 1; s < KSUP; ++s)
                            if (kv[s] > wv) { wv = kv[s]; pp = s; }
                        worst = wv; wpos = pp;
                    }
                }
            }
            thr[tid] = funsort(worst);
        } else if (t + 1 < NTIL) {
            // warps 4-7: prefetch next B tile + sq slice
            char* dst = sm + (((t + 1) & 1) ? SM_B1 : SM_B0);
            const __nv_bfloat16* src = gb + (size_t)(t + 1) * NC * CDIM;
            int t2 = tid - 128;
#pragma unroll
            for (int i = 0; i < 8; ++i) {
                int q = t2 + i * 128, rr = q >> 3, g = q & 7;
                *(uint4*)(dst + swz(rr, g)) = *(const uint4*)(src + (size_t)rr * CDIM + g * 8);
            }
            if (t2 < 32)
                *(float4*)(sqsl + ((t + 1) & 1) * 128 + t2 * 4) =
                    *(const float4*)(g_sq + (size_t)b * NPTS + (t + 1) * NC + t2 * 4);
        }
        __syncthreads();
    }

    if (tid < 128) {
        short* op = g_cand + ((size_t)b * NPTS + row0 + tid) * KSUP;
#pragma unroll
        for (int k = 0; k < KSUP; ++k) op[k] = (short)ki[k];
    }
}

// ---------------- kernel 2b: exact rescore (coalesced), top-16 ----------------
__global__ __launch_bounds__(256) void rescore_kernel() {
    __shared__ float xrow[8][CDIM];
    __shared__ float dots[8][KSUP];
    const int lane = threadIdx.x & 31;
    const int w    = threadIdx.x >> 5;
    const int b    = blockIdx.y;
    const int n    = blockIdx.x * 8 + w;
    const size_t rb = (size_t)b * NPTS + n;

    // stage own row
    *(float2*)(&xrow[w][lane * 2]) = *(const float2*)(g_xt + rb * CDIM + lane * 2);
    __syncwarp();

    const short* cp = g_cand + rb * KSUP;
    const float* xseg = &xrow[w][(lane & 3) * 16];

    // 4 groups of 8 candidates; 4 lanes per candidate (coalesced 256B rows)
#pragma unroll
    for (int g = 0; g < 4; ++g) {
        int c = g * 8 + (lane >> 2);
        int j = (int)cp[c];
        const float* yp = g_xt + ((size_t)b * NPTS + j) * CDIM + (lane & 3) * 16;
        float d = 0.f;
#pragma unroll
        for (int q = 0; q < 4; ++q) {
            float4 yv = *(const float4*)(yp + q * 4);
            float4 xv = *(const float4*)(xseg + q * 4);
            d = fmaf(xv.x, yv.x, d);
            d = fmaf(xv.y, yv.y, d);
            d = fmaf(xv.z, yv.z, d);
            d = fmaf(xv.w, yv.w, d);
        }
        d += __shfl_xor_sync(0xffffffffu, d, 1);
        d += __shfl_xor_sync(0xffffffffu, d, 2);
        if ((lane & 3) == 0) dots[w][c] = d;
    }
    __syncwarp();

    int j = (int)cp[lane];
    ull key;
    if (j == n) {
        key = ~0ULL;
    } else {
        float dist = fmaf(-2.f, dots[w][lane], g_sq[(size_t)b * NPTS + j]);
        key = ((ull)fsort(dist) << 32) | (unsigned)j;
    }
    // 32-lane bitonic sort (ascending)
#pragma unroll
    for (int k = 2; k <= 32; k <<= 1) {
#pragma unroll
        for (int jj = k >> 1; jj > 0; jj >>= 1) {
            ull other = __shfl_xor_sync(0xffffffffu, key, jj);
            bool up   = ((lane & k) == 0);
            bool low  = ((lane & jj) == 0);
            bool keep_small = (low == up);
            ull mn = key < other ? key : other;
            ull mx = key < other ? other : key;
            key = keep_small ? mn : mx;
        }
    }
    if (lane < KNBR)
        g_idx[rb * KNBR + lane] = (int)(key & 0xFFFFu);
}

// ---------------- kernel 3: A = W1.x ; Cpre = (W2-W1).x + b1+b2 ----------------
__global__ void feat_kernel(const float* __restrict__ x,
                            const float* __restrict__ W1, const float* __restrict__ b1,
                            const float* __restrict__ W2, const float* __restrict__ b2) {
    __shared__ float xs [CDIM][64];
    __shared__ float w1s[COUT][CDIM];
    __shared__ float wds[COUT][CDIM];
    __shared__ float bs [COUT];

    const int tid = threadIdx.x;
    const int b   = blockIdx.y;
    const int n0  = blockIdx.x * 64;
    const float* xb = x + (size_t)b * CDIM * NPTS;

#pragma unroll
    for (int i = 0; i < 4; ++i) {
        int q = tid + i * 256, c = q >> 4, mg = q & 15;
        *(float4*)(&xs[c][mg * 4]) = *(const float4*)(xb + c * NPTS + n0 + mg * 4);
    }
#pragma unroll
    for (int i = 0; i < 4; ++i) {
        int q = tid + i * 256, o = q >> 4, cg = (q & 15) * 4;
        float4 w1v = *(const float4*)(W1 + o * CDIM + cg);
        float4 w2v = *(const float4*)(W2 + o * CDIM + cg);
        *(float4*)(&w1s[o][cg]) = w1v;
        *(float4*)(&wds[o][cg]) = make_float4(w2v.x - w1v.x, w2v.y - w1v.y,
                                              w2v.z - w1v.z, w2v.w - w1v.w);
    }
    if (tid < COUT) bs[tid] = b1[tid] + b2[tid];
    __syncthreads();

    const int tx = tid & 15;
    const int ty = tid >> 4;
    float aA[4][4] = {}, aC[4][4] = {};
#pragma unroll 16
    for (int c = 0; c < CDIM; ++c) {
        float4 xv = *(const float4*)(&xs[c][tx * 4]);
        float xr[4] = { xv.x, xv.y, xv.z, xv.w };
#pragma unroll
        for (int jj = 0; jj < 4; ++jj) {
            float w1e = w1s[ty * 4 + jj][c];
            float wde = wds[ty * 4 + jj][c];
#pragma unroll
            for (int i = 0; i < 4; ++i) {
                aA[i][jj] = fmaf(xr[i], w1e, aA[i][jj]);
                aC[i][jj] = fmaf(xr[i], wde, aC[i][jj]);
            }
        }
    }
#pragma unroll
    for (int i = 0; i < 4; ++i) {
        int n = n0 + tx * 4 + i;
        float* ap = g_A  + ((size_t)b * NPTS + n) * COUT + ty * 4;
        float* cp = g_Cp + ((size_t)b * NPTS + n) * COUT + ty * 4;
        *(float4*)ap = make_float4(aA[i][0], aA[i][1], aA[i][2], aA[i][3]);
        *(float4*)cp = make_float4(aC[i][0] + bs[ty * 4 + 0],
                                   aC[i][1] + bs[ty * 4 + 1],
                                   aC[i][2] + bs[ty * 4 + 2],
                                   aC[i][3] + bs[ty * 4 + 3]);
    }
}

// ---------------- kernel 4: gather-max + relu (2 points/thread ILP) ----------------
__global__ __launch_bounds__(256) void gather_kernel(float* __restrict__ out) {
    const int tid = threadIdx.x;
    const int b   = blockIdx.y;
    const int l   = tid & 63;
    const int g   = tid >> 6;
    const int n1  = blockIdx.x * 128 + l;
    const int n2  = n1 + 64;
    const int* ip1 = g_idx + ((size_t)b * NPTS + n1) * KNBR;
    const int* ip2 = g_idx + ((size_t)b * NPTS + n2) * KNBR;

    float mx1[16], mx2[16];
#pragma unroll
    for (int i = 0; i < 16; ++i) { mx1[i] = -3.4e38f; mx2[i] = -3.4e38f; }

#pragma unroll
    for (int k = 0; k < KNBR; ++k) {
        int j1 = ip1[k], j2 = ip2[k];
        const float4* ap1 = (const float4*)(g_A + ((size_t)b * NPTS + j1) * COUT + g * 16);
        const float4* ap2 = (const float4*)(g_A + ((size_t)b * NPTS + j2) * COUT + g * 16);
#pragma unroll
        for (int q = 0; q < 4; ++q) {
            float4 v1 = ap1[q];
            float4 v2 = ap2[q];
            mx1[q * 4 + 0] = fmaxf(mx1[q * 4 + 0], v1.x);
            mx1[q * 4 + 1] = fmaxf(mx1[q * 4 + 1], v1.y);
            mx1[q * 4 + 2] = fmaxf(mx1[q * 4 + 2], v1.z);
            mx1[q * 4 + 3] = fmaxf(mx1[q * 4 + 3], v1.w);
            mx2[q * 4 + 0] = fmaxf(mx2[q * 4 + 0], v2.x);
            mx2[q * 4 + 1] = fmaxf(mx2[q * 4 + 1], v2.y);
            mx2[q * 4 + 2] = fmaxf(mx2[q * 4 + 2], v2.z);
            mx2[q * 4 + 3] = fmaxf(mx2[q * 4 + 3], v2.w);
        }
    }
    const float4* cp1 = (const float4*)(g_Cp + ((size_t)b * NPTS + n1) * COUT + g * 16);
    const float4* cp2 = (const float4*)(g_Cp + ((size_t)b * NPTS + n2) * COUT + g * 16);
    float* op1 = out + ((size_t)b * COUT + g * 16) * NPTS + n1;
    float* op2 = out + ((size_t)b * COUT + g * 16) * NPTS + n2;
#pragma unroll
    for (int q = 0; q < 4; ++q) {
        float4 c1 = cp1[q];
        float4 c2 = cp2[q];
        op1[(q * 4 + 0) * NPTS] = fmaxf(c1.x + mx1[q * 4 + 0], 0.f);
        op1[(q * 4 + 1) * NPTS] = fmaxf(c1.y + mx1[q * 4 + 1], 0.f);
        op1[(q * 4 + 2) * NPTS] = fmaxf(c1.z + mx1[q * 4 + 2], 0.f);
        op1[(q * 4 + 3) * NPTS] = fmaxf(c1.w + mx1[q * 4 + 3], 0.f);
        op2[(q * 4 + 0) * NPTS] = fmaxf(c2.x + mx2[q * 4 + 0], 0.f);
        op2[(q * 4 + 1) * NPTS] = fmaxf(c2.y + mx2[q * 4 + 1], 0.f);
        op2[(q * 4 + 2) * NPTS] = fmaxf(c2.z + mx2[q * 4 + 2], 0.f);
        op2[(q * 4 + 3) * NPTS] = fmaxf(c2.w + mx2[q * 4 + 3], 0.f);
    }
}

// ---------------- launch ----------------
extern "C" void kernel_launch(void* const* d_in, const int* in_sizes, int n_in,
                              void* d_out, int out_size) {
    const float *x = nullptr, *W1 = nullptr, *b1 = nullptr, *W2 = nullptr, *b2 = nullptr;
    for (int i = 0; i < n_in; ++i) {
        int s = in_sizes[i];
        const float* p = (const float*)d_in[i];
        if      (s == BATCH * CDIM * NPTS) x = p;
        else if (s == COUT * CDIM)        { if (!W1) W1 = p; else W2 = p; }
        else if (s == COUT)               { if (!b1) b1 = p; else b2 = p; }
    }
    float* out = (float*)d_out;
    (void)out_size;

    cudaFuncSetAttribute(knn_mma_kernel, cudaFuncAttributeMaxDynamicSharedMemorySize, KNN_SMEM);

    // knn placed 4th so the fixed ncu capture slot profiles it
    sq_kernel      <<<dim3(NPTS / 256, BATCH), 256>>>(x);
    tr_kernel      <<<dim3(NPTS / 32, CDIM / 32, BATCH), dim3(32, 8)>>>(x);
    feat_kernel    <<<dim3(NPTS / 64, BATCH), 256>>>(x, W1, b1, W2, b2);
    knn_mma_kernel <<<dim3(NPTS / 128, BATCH), 256, KNN_SMEM>>>();
    rescore_kernel <<<dim3(NPTS / 8, BATCH), 256>>>();
    gather_kernel  <<<dim3(NPTS / 128, BATCH), 256>>>(out);
}

// round 9
// speedup vs baseline: 2.0109x; 1.2114x over previous
#include <cuda_runtime.h>
#include <cuda_bf16.h>
#include <cstdint>

#define BATCH 8
#define CDIM  64
#define NPTS  4096
#define KNBR  16
#define COUT  64
#define KSUP  32          // candidate superset per row
#define NC    64          // candidates per tile in phase B
#define NTIL  (NPTS / NC) // 64

typedef unsigned long long ull;

// ---------------- scratch (no allocations allowed) ----------------
__device__ float          g_sq  [BATCH * NPTS];
__device__ int            g_idx [BATCH * NPTS * KNBR];
__device__ float          g_A   [BATCH * NPTS * COUT];
__device__ float          g_Cp  [BATCH * NPTS * COUT];
__device__ float          g_xt  [BATCH * NPTS * CDIM];   // point-major fp32
__device__ __nv_bfloat16  g_xh  [BATCH * NPTS * CDIM];   // point-major bf16
__device__ short          g_cand[BATCH * NPTS * KSUP];

// ---------------- helpers ----------------
__device__ __forceinline__ uint32_t smem_u32(const void* p) {
    uint32_t a;
    asm("{ .reg .u64 t; cvta.to.shared.u64 t, %1; cvt.u32.u64 %0, t; }" : "=r"(a) : "l"(p));
    return a;
}
__device__ __forceinline__ unsigned fsort(float v) {
    unsigned u = __float_as_uint(v);
    return u ^ (0x80000000u | (unsigned)((int)u >> 31));
}
__device__ __forceinline__ float funsort(unsigned s) {
    unsigned u = (s & 0x80000000u) ? (s ^ 0x80000000u) : ~s;
    return __uint_as_float(u);
}
__device__ __forceinline__ void ldmx4(uint32_t* r, uint32_t addr) {
    asm volatile("ldmatrix.sync.aligned.m8n8.x4.shared.b16 {%0,%1,%2,%3}, [%4];"
                 : "=r"(r[0]), "=r"(r[1]), "=r"(r[2]), "=r"(r[3]) : "r"(addr));
}
__device__ __forceinline__ void mma16816(float* c, const uint32_t* a, uint32_t b0, uint32_t b1) {
    asm volatile("mma.sync.aligned.m16n8k16.row.col.f32.bf16.bf16.f32 "
                 "{%0,%1,%2,%3}, {%4,%5,%6,%7}, {%8,%9}, {%0,%1,%2,%3};"
                 : "+f"(c[0]), "+f"(c[1]), "+f"(c[2]), "+f"(c[3])
                 : "r"(a[0]), "r"(a[1]), "r"(a[2]), "r"(a[3]), "r"(b0), "r"(b1));
}
__device__ __forceinline__ void cp16(uint32_t dst, const void* src) {
    asm volatile("cp.async.cg.shared.global [%0], [%1], 16;" :: "r"(dst), "l"(src));
}
// swizzled byte offset of 16B granule g (0..7) in row rr of a [rows][64bf16] tile
__device__ __forceinline__ int swz(int rr, int g) {
    return rr * 128 + ((g ^ (rr & 7)) << 4);
}

// ---------------- kernel 1: squared norms (exact fp32) ----------------
__global__ void sq_kernel(const float* __restrict__ x) {
    int b = blockIdx.y;
    int n = blockIdx.x * blockDim.x + threadIdx.x;
    const float* xp = x + (size_t)b * CDIM * NPTS + n;
    float s = 0.f;
#pragma unroll
    for (int c = 0; c < CDIM; ++c) { float v = xp[c * NPTS]; s = fmaf(v, v, s); }
    g_sq[b * NPTS + n] = s;
}

// ---------------- kernel 1b: transpose to point-major fp32 + bf16 ----------------
__global__ void tr_kernel(const float* __restrict__ x) {
    __shared__ float tile[32][33];
    const int tx = threadIdx.x, ty = threadIdx.y;
    const int n0 = blockIdx.x * 32, c0 = blockIdx.y * 32, b = blockIdx.z;
    const float* xb = x + (size_t)b * CDIM * NPTS;
#pragma unroll
    for (int i = 0; i < 4; ++i)
        tile[ty + i * 8][tx] = xb[(c0 + ty + i * 8) * NPTS + n0 + tx];
    __syncthreads();
#pragma unroll
    for (int i = 0; i < 4; ++i) {
        int n = n0 + ty + i * 8, c = c0 + tx;
        float v = tile[tx][ty + i * 8];
        size_t o = ((size_t)b * NPTS + n) * CDIM + c;
        g_xt[o] = v;
        g_xh[o] = __float2bfloat16(v);
    }
}

// ---------------- kernel 2: HMMA approx distances + top-32 superset ----------------
// pend: u32 packed keys (trunc fsort | 12-bit idx), layout [seg][slot][row]
// capacity 16/seg = structural max appends per lane per tile (8 nf x 2). No atomics.
#define SM_A    0                           // 16384
#define SM_B0   16384                       // 8192
#define SM_B1   24576                       // 8192
#define SM_SQ   32768                       // float[2][64]  = 512
#define SM_THR  33280                       // float[128]    = 512
#define SM_CNT  33792                       // int[4][128]   = 2048
#define SM_PEND 35840                       // u32[4][16][128] = 32768
#define KNN_SMEM (SM_PEND + 32768)          // 68608

__global__ __launch_bounds__(256, 2) void knn_mma_kernel() {
    extern __shared__ char sm[];
    float*    sqb  = (float*)   (sm + SM_SQ);
    float*    thr  = (float*)   (sm + SM_THR);
    int*      cnt  = (int*)     (sm + SM_CNT);
    unsigned* pend = (unsigned*)(sm + SM_PEND);

    const int tid  = threadIdx.x;
    const int w    = tid >> 5;
    const int lane = tid & 31;
    const int b    = blockIdx.y;
    const int row0 = blockIdx.x * 128;
    const uint32_t smb = smem_u32(sm);

    const __nv_bfloat16* gb = g_xh + (size_t)b * NPTS * CDIM;

    // prologue: A tile (swizzled), B tile 0, sq slice 0, thr
#pragma unroll
    for (int i = 0; i < 4; ++i) {    // A: 1024 uint4
        int q = tid + i * 256, rr = q >> 3, g = q & 7;
        *(uint4*)(sm + SM_A + swz(rr, g)) = *(const uint4*)(gb + (size_t)(row0 + rr) * CDIM + g * 8);
    }
#pragma unroll
    for (int i = 0; i < 2; ++i) {    // B0: 512 uint4 (64 rows)
        int q = tid + i * 256, rr = q >> 3, g = q & 7;
        *(uint4*)(sm + SM_B0 + swz(rr, g)) = *(const uint4*)(gb + (size_t)rr * CDIM + g * 8);
    }
    if (tid < 16)
        *(float4*)(sqb + tid * 4) = *(const float4*)(g_sq + (size_t)b * NPTS + tid * 4);
    if (tid < 128) thr[tid] = 3.4e38f;
    __syncthreads();

    // GEMM role (all 8 warps): rows wrow..wrow+15
    const int wrow = w * 16;
    const int arow = wrow + (lane & 7) + ((lane >> 3) & 1) * 8;
    const int rA   = wrow + (lane >> 2);
    const int rB   = rA + 8;
    const int seg  = lane & 3;
    const int mloc = seg * 2;

    // A fragments: block-constant, load once
    uint32_t af[4][4];
#pragma unroll
    for (int kc = 0; kc < 4; ++kc) {
        int ach = kc * 2 + (lane >> 4);
        ldmx4(af[kc], smb + SM_A + swz(arow, ach));
    }

    // selection state (threads 0..127 own row = row0 + tid), packed u32 keys
    unsigned kvi[KSUP];
    unsigned worst = 0xFFFFFFFFu; int wpos = 0;
#pragma unroll
    for (int s = 0; s < KSUP; ++s) kvi[s] = 0xFFFFFFFFu;

    for (int t = 0; t < NTIL; ++t) {
        const uint32_t bbase = smb + ((t & 1) ? SM_B1 : SM_B0);
        const float*   sql   = sqb + (t & 1) * 64;
        const float thrA = thr[rA];
        const float thrB = thr[rB];
        const int   tb   = t * NC;
        int cA = 0, cB = 0;   // register counters; <=16 by construction

#pragma unroll
        for (int nf = 0; nf < 8; ++nf) {
            int brow = nf * 8 + (lane & 7);
            int bg   = lane >> 3;
            uint32_t p[4], q4[4];
            ldmx4(p,  bbase + swz(brow, bg));
            ldmx4(q4, bbase + swz(brow, bg + 4));
            float acc[4] = {0.f, 0.f, 0.f, 0.f};
            mma16816(acc, af[0], p[0],  p[1]);
            mma16816(acc, af[1], p[2],  p[3]);
            mma16816(acc, af[2], q4[0], q4[1]);
            mma16816(acc, af[3], q4[2], q4[3]);

            // fused epilogue: atomic-free threshold/append, packed u32 keys
            int   ml = mloc + nf * 8;
            float s0 = sql[ml], s1 = sql[ml + 1];
            int   m0 = tb + ml;
            float v00 = fmaf(-2.f, acc[0], s0);
            float v01 = fmaf(-2.f, acc[1], s1);
            float v10 = fmaf(-2.f, acc[2], s0);
            float v11 = fmaf(-2.f, acc[3], s1);
            if (v00 <= thrA) pend[(seg * 16 + cA++) * 128 + rA] = (fsort(v00) & 0xFFFFF000u) | (unsigned)m0;
            if (v01 <= thrA) pend[(seg * 16 + cA++) * 128 + rA] = (fsort(v01) & 0xFFFFF000u) | (unsigned)(m0 + 1);
            if (v10 <= thrB) pend[(seg * 16 + cB++) * 128 + rB] = (fsort(v10) & 0xFFFFF000u) | (unsigned)m0;
            if (v11 <= thrB) pend[(seg * 16 + cB++) * 128 + rB] = (fsort(v11) & 0xFFFFF000u) | (unsigned)(m0 + 1);
        }
        cnt[seg * 128 + rA] = cA;
        cnt[seg * 128 + rB] = cB;
        __syncthreads();   // pend + cnt visible

        if (tid < 128) {
            // coherent flush: thread tid owns row tid; 4 segments, conflict-free LDS
#pragma unroll
            for (int sg = 0; sg < 4; ++sg) {
                unsigned myc  = (unsigned)cnt[sg * 128 + tid];
                unsigned cmax = __reduce_max_sync(0xffffffffu, myc);
                for (unsigned j = 0; j < cmax; ++j) {
                    unsigned kn = (j < myc) ? pend[(sg * 16 + (int)j) * 128 + tid] : 0xFFFFFFFFu;
                    bool take = kn < worst;
                    if (__any_sync(0xffffffffu, take)) {
#pragma unroll
                        for (int s = 0; s < KSUP; ++s)
                            if (take && s == wpos) kvi[s] = kn;
                        unsigned wv = kvi[0]; int pp = 0;
#pragma unroll
                        for (int s = 1; s < KSUP; ++s)
                            if (kvi[s] > wv) { wv = kvi[s]; pp = s; }
                        worst = wv; wpos = pp;
                    }
                }
            }
            thr[tid] = funsort(worst | 0xFFFu);
        } else if (t + 1 < NTIL) {
            // warps 4-7: async prefetch next B tile + sq slice
            const int t2 = tid - 128;
            uint32_t dstb = smb + (((t + 1) & 1) ? SM_B1 : SM_B0);
            const __nv_bfloat16* src = gb + (size_t)(t + 1) * NC * CDIM;
#pragma unroll
            for (int i = 0; i < 4; ++i) {
                int q = t2 + i * 128, rr = q >> 3, g = q & 7;
                cp16(dstb + swz(rr, g), src + (size_t)rr * CDIM + g * 8);
            }
            if (t2 < 16)
                cp16(smb + SM_SQ + (((t + 1) & 1) * 64 + t2 * 4) * 4,
                     g_sq + (size_t)b * NPTS + (t + 1) * NC + t2 * 4);
            asm volatile("cp.async.commit_group;");
            asm volatile("cp.async.wait_group 0;");
        }
        __syncthreads();   // flush done (thr updated), B(t+1) ready, pend reusable
    }

    if (tid < 128) {
        short* op = g_cand + ((size_t)b * NPTS + row0 + tid) * KSUP;
#pragma unroll
        for (int k = 0; k < KSUP; ++k) op[k] = (short)(kvi[k] & 0xFFFu);
    }
}

// ---------------- kernel 2b: exact rescore (coalesced), top-16 ----------------
__global__ __launch_bounds__(256) void rescore_kernel() {
    __shared__ float xrow[8][CDIM];
    __shared__ float dots[8][KSUP];
    const int lane = threadIdx.x & 31;
    const int w    = threadIdx.x >> 5;
    const int b    = blockIdx.y;
    const int n    = blockIdx.x * 8 + w;
    const size_t rb = (size_t)b * NPTS + n;

    *(float2*)(&xrow[w][lane * 2]) = *(const float2*)(g_xt + rb * CDIM + lane * 2);
    __syncwarp();

    const short* cp = g_cand + rb * KSUP;
    const float* xseg = &xrow[w][(lane & 3) * 16];

#pragma unroll
    for (int g = 0; g < 4; ++g) {
        int c = g * 8 + (lane >> 2);
        int j = (int)cp[c];
        const float* yp = g_xt + ((size_t)b * NPTS + j) * CDIM + (lane & 3) * 16;
        float d = 0.f;
#pragma unroll
        for (int q = 0; q < 4; ++q) {
            float4 yv = *(const float4*)(yp + q * 4);
            float4 xv = *(const float4*)(xseg + q * 4);
            d = fmaf(xv.x, yv.x, d);
            d = fmaf(xv.y, yv.y, d);
            d = fmaf(xv.z, yv.z, d);
            d = fmaf(xv.w, yv.w, d);
        }
        d += __shfl_xor_sync(0xffffffffu, d, 1);
        d += __shfl_xor_sync(0xffffffffu, d, 2);
        if ((lane & 3) == 0) dots[w][c] = d;
    }
    __syncwarp();

    int j = (int)cp[lane];
    ull key;
    if (j == n) {
        key = ~0ULL;
    } else {
        float dist = fmaf(-2.f, dots[w][lane], g_sq[(size_t)b * NPTS + j]);
        key = ((ull)fsort(dist) << 32) | (unsigned)j;
    }
#pragma unroll
    for (int k = 2; k <= 32; k <<= 1) {
#pragma unroll
        for (int jj = k >> 1; jj > 0; jj >>= 1) {
            ull other = __shfl_xor_sync(0xffffffffu, key, jj);
            bool up   = ((lane & k) == 0);
            bool low  = ((lane & jj) == 0);
            bool keep_small = (low == up);
            ull mn = key < other ? key : other;
            ull mx = key < other ? other : key;
            key = keep_small ? mn : mx;
        }
    }
    if (lane < KNBR)
        g_idx[rb * KNBR + lane] = (int)(key & 0xFFFFu);
}

// ---------------- kernel 3: A = W1.x ; Cpre = (W2-W1).x + b1+b2 ----------------
__global__ void feat_kernel(const float* __restrict__ x,
                            const float* __restrict__ W1, const float* __restrict__ b1,
                            const float* __restrict__ W2, const float* __restrict__ b2) {
    __shared__ float xs [CDIM][64];
    __shared__ float w1s[COUT][CDIM];
    __shared__ float wds[COUT][CDIM];
    __shared__ float bs [COUT];

    const int tid = threadIdx.x;
    const int b   = blockIdx.y;
    const int n0  = blockIdx.x * 64;
    const float* xb = x + (size_t)b * CDIM * NPTS;

#pragma unroll
    for (int i = 0; i < 4; ++i) {
        int q = tid + i * 256, c = q >> 4, mg = q & 15;
        *(float4*)(&xs[c][mg * 4]) = *(const float4*)(xb + c * NPTS + n0 + mg * 4);
    }
#pragma unroll
    for (int i = 0; i < 4; ++i) {
        int q = tid + i * 256, o = q >> 4, cg = (q & 15) * 4;
        float4 w1v = *(const float4*)(W1 + o * CDIM + cg);
        float4 w2v = *(const float4*)(W2 + o * CDIM + cg);
        *(float4*)(&w1s[o][cg]) = w1v;
        *(float4*)(&wds[o][cg]) = make_float4(w2v.x - w1v.x, w2v.y - w1v.y,
                                              w2v.z - w1v.z, w2v.w - w1v.w);
    }
    if (tid < COUT) bs[tid] = b1[tid] + b2[tid];
    __syncthreads();

    const int tx = tid & 15;
    const int ty = tid >> 4;
    float aA[4][4] = {}, aC[4][4] = {};
#pragma unroll 16
    for (int c = 0; c < CDIM; ++c) {
        float4 xv = *(const float4*)(&xs[c][tx * 4]);
        float xr[4] = { xv.x, xv.y, xv.z, xv.w };
#pragma unroll
        for (int jj = 0; jj < 4; ++jj) {
            float w1e = w1s[ty * 4 + jj][c];
            float wde = wds[ty * 4 + jj][c];
#pragma unroll
            for (int i = 0; i < 4; ++i) {
                aA[i][jj] = fmaf(xr[i], w1e, aA[i][jj]);
                aC[i][jj] = fmaf(xr[i], wde, aC[i][jj]);
            }
        }
    }
#pragma unroll
    for (int i = 0; i < 4; ++i) {
        int n = n0 + tx * 4 + i;
        float* ap = g_A  + ((size_t)b * NPTS + n) * COUT + ty * 4;
        float* cp = g_Cp + ((size_t)b * NPTS + n) * COUT + ty * 4;
        *(float4*)ap = make_float4(aA[i][0], aA[i][1], aA[i][2], aA[i][3]);
        *(float4*)cp = make_float4(aC[i][0] + bs[ty * 4 + 0],
                                   aC[i][1] + bs[ty * 4 + 1],
                                   aC[i][2] + bs[ty * 4 + 2],
                                   aC[i][3] + bs[ty * 4 + 3]);
    }
}

// ---------------- kernel 4: gather-max + relu (2 points/thread ILP) ----------------
__global__ __launch_bounds__(256) void gather_kernel(float* __restrict__ out) {
    const int tid = threadIdx.x;
    const int b   = blockIdx.y;
    const int l   = tid & 63;
    const int g   = tid >> 6;
    const int n1  = blockIdx.x * 128 + l;
    const int n2  = n1 + 64;
    const int* ip1 = g_idx + ((size_t)b * NPTS + n1) * KNBR;
    const int* ip2 = g_idx + ((size_t)b * NPTS + n2) * KNBR;

    float mx1[16], mx2[16];
#pragma unroll
    for (int i = 0; i < 16; ++i) { mx1[i] = -3.4e38f; mx2[i] = -3.4e38f; }

#pragma unroll
    for (int k = 0; k < KNBR; ++k) {
        int j1 = ip1[k], j2 = ip2[k];
        const float4* ap1 = (const float4*)(g_A + ((size_t)b * NPTS + j1) * COUT + g * 16);
        const float4* ap2 = (const float4*)(g_A + ((size_t)b * NPTS + j2) * COUT + g * 16);
#pragma unroll
        for (int q = 0; q < 4; ++q) {
            float4 v1 = ap1[q];
            float4 v2 = ap2[q];
            mx1[q * 4 + 0] = fmaxf(mx1[q * 4 + 0], v1.x);
            mx1[q * 4 + 1] = fmaxf(mx1[q * 4 + 1], v1.y);
            mx1[q * 4 + 2] = fmaxf(mx1[q * 4 + 2], v1.z);
            mx1[q * 4 + 3] = fmaxf(mx1[q * 4 + 3], v1.w);
            mx2[q * 4 + 0] = fmaxf(mx2[q * 4 + 0], v2.x);
            mx2[q * 4 + 1] = fmaxf(mx2[q * 4 + 1], v2.y);
            mx2[q * 4 + 2] = fmaxf(mx2[q * 4 + 2], v2.z);
            mx2[q * 4 + 3] = fmaxf(mx2[q * 4 + 3], v2.w);
        }
    }
    const float4* cp1 = (const float4*)(g_Cp + ((size_t)b * NPTS + n1) * COUT + g * 16);
    const float4* cp2 = (const float4*)(g_Cp + ((size_t)b * NPTS + n2) * COUT + g * 16);
    float* op1 = out + ((size_t)b * COUT + g * 16) * NPTS + n1;
    float* op2 = out + ((size_t)b * COUT + g * 16) * NPTS + n2;
#pragma unroll
    for (int q = 0; q < 4; ++q) {
        float4 c1 = cp1[q];
        float4 c2 = cp2[q];
        op1[(q * 4 + 0) * NPTS] = fmaxf(c1.x + mx1[q * 4 + 0], 0.f);
        op1[(q * 4 + 1) * NPTS] = fmaxf(c1.y + mx1[q * 4 + 1], 0.f);
        op1[(q * 4 + 2) * NPTS] = fmaxf(c1.z + mx1[q * 4 + 2], 0.f);
        op1[(q * 4 + 3) * NPTS] = fmaxf(c1.w + mx1[q * 4 + 3], 0.f);
        op2[(q * 4 + 0) * NPTS] = fmaxf(c2.x + mx2[q * 4 + 0], 0.f);
        op2[(q * 4 + 1) * NPTS] = fmaxf(c2.y + mx2[q * 4 + 1], 0.f);
        op2[(q * 4 + 2) * NPTS] = fmaxf(c2.z + mx2[q * 4 + 2], 0.f);
        op2[(q * 4 + 3) * NPTS] = fmaxf(c2.w + mx2[q * 4 + 3], 0.f);
    }
}

// ---------------- launch ----------------
extern "C" void kernel_launch(void* const* d_in, const int* in_sizes, int n_in,
                              void* d_out, int out_size) {
    const float *x = nullptr, *W1 = nullptr, *b1 = nullptr, *W2 = nullptr, *b2 = nullptr;
    for (int i = 0; i < n_in; ++i) {
        int s = in_sizes[i];
        const float* p = (const float*)d_in[i];
        if      (s == BATCH * CDIM * NPTS) x = p;
        else if (s == COUT * CDIM)        { if (!W1) W1 = p; else W2 = p; }
        else if (s == COUT)               { if (!b1) b1 = p; else b2 = p; }
    }
    float* out = (float*)d_out;
    (void)out_size;

    cudaFuncSetAttribute(knn_mma_kernel, cudaFuncAttributeMaxDynamicSharedMemorySize, KNN_SMEM);

    // knn placed 4th so the fixed ncu capture slot profiles it
    sq_kernel      <<<dim3(NPTS / 256, BATCH), 256>>>(x);
    tr_kernel      <<<dim3(NPTS / 32, CDIM / 32, BATCH), dim3(32, 8)>>>(x);
    feat_kernel    <<<dim3(NPTS / 64, BATCH), 256>>>(x, W1, b1, W2, b2);
    knn_mma_kernel <<<dim3(NPTS / 128, BATCH), 256, KNN_SMEM>>>();
    rescore_kernel <<<dim3(NPTS / 8, BATCH), 256>>>();
    gather_kernel  <<<dim3(NPTS / 128, BATCH), 256>>>(out);
}

// round 10
// speedup vs baseline: 2.0197x; 1.0044x over previous
#include <cuda_runtime.h>
#include <cuda_bf16.h>
#include <cstdint>

#define BATCH 8
#define CDIM  64
#define NPTS  4096
#define KNBR  16
#define COUT  64
#define KSUP  32          // candidate superset per row
#define NC    64          // candidates per tile in phase B
#define NTIL  (NPTS / NC) // 64

typedef unsigned long long ull;

// ---------------- scratch (no allocations allowed) ----------------
__device__ float          g_sq  [BATCH * NPTS];
__device__ int            g_idx [BATCH * NPTS * KNBR];
__device__ float          g_A   [BATCH * NPTS * COUT];
__device__ float          g_Cp  [BATCH * NPTS * COUT];
__device__ float          g_xt  [BATCH * NPTS * CDIM];   // point-major fp32
__device__ __nv_bfloat16  g_xh  [BATCH * NPTS * CDIM];   // point-major bf16
__device__ short          g_cand[BATCH * NPTS * KSUP];

// ---------------- helpers ----------------
__device__ __forceinline__ uint32_t smem_u32(const void* p) {
    uint32_t a;
    asm("{ .reg .u64 t; cvta.to.shared.u64 t, %1; cvt.u32.u64 %0, t; }" : "=r"(a) : "l"(p));
    return a;
}
__device__ __forceinline__ unsigned fsort(float v) {
    unsigned u = __float_as_uint(v);
    return u ^ (0x80000000u | (unsigned)((int)u >> 31));
}
__device__ __forceinline__ float funsort(unsigned s) {
    unsigned u = (s & 0x80000000u) ? (s ^ 0x80000000u) : ~s;
    return __uint_as_float(u);
}
__device__ __forceinline__ void ldmx4(uint32_t* r, uint32_t addr) {
    asm volatile("ldmatrix.sync.aligned.m8n8.x4.shared.b16 {%0,%1,%2,%3}, [%4];"
                 : "=r"(r[0]), "=r"(r[1]), "=r"(r[2]), "=r"(r[3]) : "r"(addr));
}
__device__ __forceinline__ void mma16816(float* c, const uint32_t* a, uint32_t b0, uint32_t b1) {
    asm volatile("mma.sync.aligned.m16n8k16.row.col.f32.bf16.bf16.f32 "
                 "{%0,%1,%2,%3}, {%4,%5,%6,%7}, {%8,%9}, {%0,%1,%2,%3};"
                 : "+f"(c[0]), "+f"(c[1]), "+f"(c[2]), "+f"(c[3])
                 : "r"(a[0]), "r"(a[1]), "r"(a[2]), "r"(a[3]), "r"(b0), "r"(b1));
}
__device__ __forceinline__ void cp16(uint32_t dst, const void* src) {
    asm volatile("cp.async.cg.shared.global [%0], [%1], 16;" :: "r"(dst), "l"(src));
}
// swizzled byte offset of 16B granule g (0..7) in row rr of a [rows][64bf16] tile
__device__ __forceinline__ int swz(int rr, int g) {
    return rr * 128 + ((g ^ (rr & 7)) << 4);
}
#define BAR_ARRIVE(id, n) asm volatile("bar.arrive %0, %1;" :: "r"(id), "r"(n) : "memory")
#define BAR_SYNC(id, n)   asm volatile("bar.sync %0, %1;"   :: "r"(id), "r"(n) : "memory")
#define MEMBAR_CTA()      asm volatile("membar.cta;" ::: "memory")

// ---------------- kernel 1: squared norms (exact fp32) ----------------
__global__ void sq_kernel(const float* __restrict__ x) {
    int b = blockIdx.y;
    int n = blockIdx.x * blockDim.x + threadIdx.x;
    const float* xp = x + (size_t)b * CDIM * NPTS + n;
    float s = 0.f;
#pragma unroll
    for (int c = 0; c < CDIM; ++c) { float v = xp[c * NPTS]; s = fmaf(v, v, s); }
    g_sq[b * NPTS + n] = s;
}

// ---------------- kernel 1b: transpose to point-major fp32 + bf16 ----------------
__global__ void tr_kernel(const float* __restrict__ x) {
    __shared__ float tile[32][33];
    const int tx = threadIdx.x, ty = threadIdx.y;
    const int n0 = blockIdx.x * 32, c0 = blockIdx.y * 32, b = blockIdx.z;
    const float* xb = x + (size_t)b * CDIM * NPTS;
#pragma unroll
    for (int i = 0; i < 4; ++i)
        tile[ty + i * 8][tx] = xb[(c0 + ty + i * 8) * NPTS + n0 + tx];
    __syncthreads();
#pragma unroll
    for (int i = 0; i < 4; ++i) {
        int n = n0 + ty + i * 8, c = c0 + tx;
        float v = tile[tx][ty + i * 8];
        size_t o = ((size_t)b * NPTS + n) * CDIM + c;
        g_xt[o] = v;
        g_xh[o] = __float2bfloat16(v);
    }
}

// ---------------- kernel 2: warp-specialized HMMA distances + top-32 ----------------
// Producers: warps 0-3 (32 rows each), consumers: warps 4-7 (1 row/thread).
// pend double-buffered; named barriers per parity overlap flush(t) with gemm(t+1).
#define SM_A    0                           // 16384
#define SM_B0   16384                       // 8192
#define SM_B1   24576                       // 8192
#define SM_SQ   32768                       // float[2][64]  = 512
#define SM_THR  33280                       // float[128]    = 512
#define SM_CNT  33792                       // int[2][4][128]  = 4096
#define SM_PEND 37888                       // u32[2][4][16][128] = 65536
#define KNN_SMEM (SM_PEND + 65536)          // 103424

__global__ __launch_bounds__(256, 2) void knn_mma_kernel() {
    extern __shared__ char sm[];
    float*    sqb  = (float*)   (sm + SM_SQ);
    float*    thr  = (float*)   (sm + SM_THR);
    int*      cnt  = (int*)     (sm + SM_CNT);
    unsigned* pend = (unsigned*)(sm + SM_PEND);

    const int tid  = threadIdx.x;
    const int w    = tid >> 5;
    const int lane = tid & 31;
    const int b    = blockIdx.y;
    const int row0 = blockIdx.x * 128;
    const uint32_t smb = smem_u32(sm);

    const __nv_bfloat16* gb = g_xh + (size_t)b * NPTS * CDIM;

    // prologue: A tile (swizzled), B tile 0, sq slice 0, thr
#pragma unroll
    for (int i = 0; i < 4; ++i) {    // A: 1024 uint4
        int q = tid + i * 256, rr = q >> 3, g = q & 7;
        *(uint4*)(sm + SM_A + swz(rr, g)) = *(const uint4*)(gb + (size_t)(row0 + rr) * CDIM + g * 8);
    }
#pragma unroll
    for (int i = 0; i < 2; ++i) {    // B0: 512 uint4 (64 rows)
        int q = tid + i * 256, rr = q >> 3, g = q & 7;
        *(uint4*)(sm + SM_B0 + swz(rr, g)) = *(const uint4*)(gb + (size_t)rr * CDIM + g * 8);
    }
    if (tid < 16)
        *(float4*)(sqb + tid * 4) = *(const float4*)(g_sq + (size_t)b * NPTS + tid * 4);
    if (tid < 128) thr[tid] = 3.4e38f;
    __syncthreads();

    if (w < 4) {
        // ================= producer role: GEMM + threshold append =================
        const int wrow = w * 32;
        const int seg  = lane & 3;
        const int mloc = seg * 2;
        const int rA0 = wrow + (lane >> 2), rB0 = rA0 + 8;
        const int rA1 = rA0 + 16,           rB1 = rA0 + 24;

        uint32_t af[2][4][4];
#pragma unroll
        for (int f = 0; f < 2; ++f) {
            int arow = wrow + f * 16 + (lane & 7) + ((lane >> 3) & 1) * 8;
#pragma unroll
            for (int kc = 0; kc < 4; ++kc) {
                int ach = kc * 2 + (lane >> 4);
                ldmx4(af[f][kc], smb + SM_A + swz(arow, ach));
            }
        }

        for (int t = 0; t < NTIL; ++t) {
            const int buf = t & 1;
            if (t >= 2) BAR_SYNC(3 + buf, 256);          // pend[buf] free (flush t-2 done)

            // prefetch B(t+1)+sq(t+1) into other buffer (async)
            if (t + 1 < NTIL) {
                uint32_t dstb = smb + ((buf ^ 1) ? SM_B1 : SM_B0);
                const __nv_bfloat16* src = gb + (size_t)(t + 1) * NC * CDIM;
#pragma unroll
                for (int i = 0; i < 4; ++i) {
                    int q = tid + i * 128, rr = q >> 3, g = q & 7;
                    cp16(dstb + swz(rr, g), src + (size_t)rr * CDIM + g * 8);
                }
                if (tid < 16)
                    cp16(smb + SM_SQ + ((buf ^ 1) * 64 + tid * 4) * 4,
                         g_sq + (size_t)b * NPTS + (t + 1) * NC + tid * 4);
                asm volatile("cp.async.commit_group;");
                asm volatile("cp.async.wait_group 1;");   // B(t) group done
            } else {
                asm volatile("cp.async.wait_group 0;");
            }
            BAR_SYNC(5, 128);                             // B(t) visible to all producers

            const uint32_t bbase = smb + (buf ? SM_B1 : SM_B0);
            const float*   sql   = sqb + buf * 64;
            const float thrA0 = thr[rA0], thrB0 = thr[rB0];
            const float thrA1 = thr[rA1], thrB1 = thr[rB1];
            int cA0 = 0, cB0 = 0, cA1 = 0, cB1 = 0;
            const int pbase = (buf * 4 + seg) * 16;

#pragma unroll
            for (int nf = 0; nf < 8; ++nf) {
                int brow = nf * 8 + (lane & 7);
                int bg   = lane >> 3;
                uint32_t p[4], q4[4];
                ldmx4(p,  bbase + swz(brow, bg));
                ldmx4(q4, bbase + swz(brow, bg + 4));

                int   ml = mloc + nf * 8;
                float s0 = sql[ml], s1 = sql[ml + 1];
                int   m0 = t * NC + ml;

                float acc0[4] = {0.f, 0.f, 0.f, 0.f};
                mma16816(acc0, af[0][0], p[0],  p[1]);
                mma16816(acc0, af[0][1], p[2],  p[3]);
                mma16816(acc0, af[0][2], q4[0], q4[1]);
                mma16816(acc0, af[0][3], q4[2], q4[3]);
                {
                    float v00 = fmaf(-2.f, acc0[0], s0);
                    float v01 = fmaf(-2.f, acc0[1], s1);
                    float v10 = fmaf(-2.f, acc0[2], s0);
                    float v11 = fmaf(-2.f, acc0[3], s1);
                    if (v00 <= thrA0) pend[(pbase + cA0++) * 128 + rA0] = (fsort(v00) & 0xFFFFF000u) | (unsigned)m0;
                    if (v01 <= thrA0) pend[(pbase + cA0++) * 128 + rA0] = (fsort(v01) & 0xFFFFF000u) | (unsigned)(m0 + 1);
                    if (v10 <= thrB0) pend[(pbase + cB0++) * 128 + rB0] = (fsort(v10) & 0xFFFFF000u) | (unsigned)m0;
                    if (v11 <= thrB0) pend[(pbase + cB0++) * 128 + rB0] = (fsort(v11) & 0xFFFFF000u) | (unsigned)(m0 + 1);
                }
                float acc1[4] = {0.f, 0.f, 0.f, 0.f};
                mma16816(acc1, af[1][0], p[0],  p[1]);
                mma16816(acc1, af[1][1], p[2],  p[3]);
                mma16816(acc1, af[1][2], q4[0], q4[1]);
                mma16816(acc1, af[1][3], q4[2], q4[3]);
                {
                    float v00 = fmaf(-2.f, acc1[0], s0);
                    float v01 = fmaf(-2.f, acc1[1], s1);
                    float v10 = fmaf(-2.f, acc1[2], s0);
                    float v11 = fmaf(-2.f, acc1[3], s1);
                    if (v00 <= thrA1) pend[(pbase + cA1++) * 128 + rA1] = (fsort(v00) & 0xFFFFF000u) | (unsigned)m0;
                    if (v01 <= thrA1) pend[(pbase + cA1++) * 128 + rA1] = (fsort(v01) & 0xFFFFF000u) | (unsigned)(m0 + 1);
                    if (v10 <= thrB1) pend[(pbase + cB1++) * 128 + rB1] = (fsort(v10) & 0xFFFFF000u) | (unsigned)m0;
                    if (v11 <= thrB1) pend[(pbase + cB1++) * 128 + rB1] = (fsort(v11) & 0xFFFFF000u) | (unsigned)(m0 + 1);
                }
            }
            cnt[(buf * 4 + seg) * 128 + rA0] = cA0;
            cnt[(buf * 4 + seg) * 128 + rB0] = cB0;
            cnt[(buf * 4 + seg) * 128 + rA1] = cA1;
            cnt[(buf * 4 + seg) * 128 + rB1] = cB1;
            MEMBAR_CTA();
            BAR_ARRIVE(1 + buf, 256);                     // gemm_done(t)
        }
    } else {
        // ================= consumer role: coherent top-32 flush =================
        const int r = tid - 128;
        unsigned kvi[KSUP];
        unsigned worst = 0xFFFFFFFFu; int wpos = 0;
#pragma unroll
        for (int s = 0; s < KSUP; ++s) kvi[s] = 0xFFFFFFFFu;

        for (int t = 0; t < NTIL; ++t) {
            const int buf = t & 1;
            BAR_SYNC(1 + buf, 256);                       // wait gemm_done(t)
#pragma unroll
            for (int sg = 0; sg < 4; ++sg) {
                unsigned myc  = (unsigned)cnt[(buf * 4 + sg) * 128 + r];
                unsigned cmax = __reduce_max_sync(0xffffffffu, myc);
                for (unsigned j = 0; j < cmax; ++j) {
                    unsigned kn = (j < myc) ? pend[((buf * 4 + sg) * 16 + (int)j) * 128 + r]
                                            : 0xFFFFFFFFu;
                    bool take = kn < worst;
                    if (__any_sync(0xffffffffu, take)) {
#pragma unroll
                        for (int s = 0; s < KSUP; ++s)
                            if (take && s == wpos) kvi[s] = kn;
                        unsigned wv = kvi[0]; int pp = 0;
#pragma unroll
                        for (int s = 1; s < KSUP; ++s)
                            if (kvi[s] > wv) { wv = kvi[s]; pp = s; }
                        worst = wv; wpos = pp;
                    }
                }
            }
            thr[r] = funsort(worst | 0xFFFu);
            MEMBAR_CTA();
            if (t + 2 < NTIL) BAR_ARRIVE(3 + buf, 256);   // flush_done(t): pend[buf] free
        }

        short* op = g_cand + ((size_t)b * NPTS + row0 + r) * KSUP;
#pragma unroll
        for (int k = 0; k < KSUP; ++k) op[k] = (short)(kvi[k] & 0xFFFu);
    }
}

// ---------------- kernel 2b: exact rescore (coalesced), top-16 ----------------
__global__ __launch_bounds__(256) void rescore_kernel() {
    __shared__ float xrow[8][CDIM];
    __shared__ float dots[8][KSUP];
    const int lane = threadIdx.x & 31;
    const int w    = threadIdx.x >> 5;
    const int b    = blockIdx.y;
    const int n    = blockIdx.x * 8 + w;
    const size_t rb = (size_t)b * NPTS + n;

    *(float2*)(&xrow[w][lane * 2]) = *(const float2*)(g_xt + rb * CDIM + lane * 2);
    __syncwarp();

    const short* cp = g_cand + rb * KSUP;
    const float* xseg = &xrow[w][(lane & 3) * 16];

#pragma unroll
    for (int g = 0; g < 4; ++g) {
        int c = g * 8 + (lane >> 2);
        int j = (int)cp[c];
        const float* yp = g_xt + ((size_t)b * NPTS + j) * CDIM + (lane & 3) * 16;
        float d = 0.f;
#pragma unroll
        for (int q = 0; q < 4; ++q) {
            float4 yv = *(const float4*)(yp + q * 4);
            float4 xv = *(const float4*)(xseg + q * 4);
            d = fmaf(xv.x, yv.x, d);
            d = fmaf(xv.y, yv.y, d);
            d = fmaf(xv.z, yv.z, d);
            d = fmaf(xv.w, yv.w, d);
        }
        d += __shfl_xor_sync(0xffffffffu, d, 1);
        d += __shfl_xor_sync(0xffffffffu, d, 2);
        if ((lane & 3) == 0) dots[w][c] = d;
    }
    __syncwarp();

    int j = (int)cp[lane];
    ull key;
    if (j == n) {
        key = ~0ULL;
    } else {
        float dist = fmaf(-2.f, dots[w][lane], g_sq[(size_t)b * NPTS + j]);
        key = ((ull)fsort(dist) << 32) | (unsigned)j;
    }
#pragma unroll
    for (int k = 2; k <= 32; k <<= 1) {
#pragma unroll
        for (int jj = k >> 1; jj > 0; jj >>= 1) {
            ull other = __shfl_xor_sync(0xffffffffu, key, jj);
            bool up   = ((lane & k) == 0);
            bool low  = ((lane & jj) == 0);
            bool keep_small = (low == up);
            ull mn = key < other ? key : other;
            ull mx = key < other ? other : key;
            key = keep_small ? mn : mx;
        }
    }
    if (lane < KNBR)
        g_idx[rb * KNBR + lane] = (int)(key & 0xFFFFu);
}

// ---------------- kernel 3: A = W1.x ; Cpre = (W2-W1).x + b1+b2 ----------------
__global__ void feat_kernel(const float* __restrict__ x,
                            const float* __restrict__ W1, const float* __restrict__ b1,
                            const float* __restrict__ W2, const float* __restrict__ b2) {
    __shared__ float xs [CDIM][64];
    __shared__ float w1s[COUT][CDIM];
    __shared__ float wds[COUT][CDIM];
    __shared__ float bs [COUT];

    const int tid = threadIdx.x;
    const int b   = blockIdx.y;
    const int n0  = blockIdx.x * 64;
    const float* xb = x + (size_t)b * CDIM * NPTS;

#pragma unroll
    for (int i = 0; i < 4; ++i) {
        int q = tid + i * 256, c = q >> 4, mg = q & 15;
        *(float4*)(&xs[c][mg * 4]) = *(const float4*)(xb + c * NPTS + n0 + mg * 4);
    }
#pragma unroll
    for (int i = 0; i < 4; ++i) {
        int q = tid + i * 256, o = q >> 4, cg = (q & 15) * 4;
        float4 w1v = *(const float4*)(W1 + o * CDIM + cg);
        float4 w2v = *(const float4*)(W2 + o * CDIM + cg);
        *(float4*)(&w1s[o][cg]) = w1v;
        *(float4*)(&wds[o][cg]) = make_float4(w2v.x - w1v.x, w2v.y - w1v.y,
                                              w2v.z - w1v.z, w2v.w - w1v.w);
    }
    if (tid < COUT) bs[tid] = b1[tid] + b2[tid];
    __syncthreads();

    const int tx = tid & 15;
    const int ty = tid >> 4;
    float aA[4][4] = {}, aC[4][4] = {};
#pragma unroll 16
    for (int c = 0; c < CDIM; ++c) {
        float4 xv = *(const float4*)(&xs[c][tx * 4]);
        float xr[4] = { xv.x, xv.y, xv.z, xv.w };
#pragma unroll
        for (int jj = 0; jj < 4; ++jj) {
            float w1e = w1s[ty * 4 + jj][c];
            float wde = wds[ty * 4 + jj][c];
#pragma unroll
            for (int i = 0; i < 4; ++i) {
                aA[i][jj] = fmaf(xr[i], w1e, aA[i][jj]);
                aC[i][jj] = fmaf(xr[i], wde, aC[i][jj]);
            }
        }
    }
#pragma unroll
    for (int i = 0; i < 4; ++i) {
        int n = n0 + tx * 4 + i;
        float* ap = g_A  + ((size_t)b * NPTS + n) * COUT + ty * 4;
        float* cp = g_Cp + ((size_t)b * NPTS + n) * COUT + ty * 4;
        *(float4*)ap = make_float4(aA[i][0], aA[i][1], aA[i][2], aA[i][3]);
        *(float4*)cp = make_float4(aC[i][0] + bs[ty * 4 + 0],
                                   aC[i][1] + bs[ty * 4 + 1],
                                   aC[i][2] + bs[ty * 4 + 2],
                                   aC[i][3] + bs[ty * 4 + 3]);
    }
}

// ---------------- kernel 4: gather-max + relu (2 points/thread ILP) ----------------
__global__ __launch_bounds__(256) void gather_kernel(float* __restrict__ out) {
    const int tid = threadIdx.x;
    const int b   = blockIdx.y;
    const int l   = tid & 63;
    const int g   = tid >> 6;
    const int n1  = blockIdx.x * 128 + l;
    const int n2  = n1 + 64;
    const int* ip1 = g_idx + ((size_t)b * NPTS + n1) * KNBR;
    const int* ip2 = g_idx + ((size_t)b * NPTS + n2) * KNBR;

    float mx1[16], mx2[16];
#pragma unroll
    for (int i = 0; i < 16; ++i) { mx1[i] = -3.4e38f; mx2[i] = -3.4e38f; }

#pragma unroll
    for (int k = 0; k < KNBR; ++k) {
        int j1 = ip1[k], j2 = ip2[k];
        const float4* ap1 = (const float4*)(g_A + ((size_t)b * NPTS + j1) * COUT + g * 16);
        const float4* ap2 = (const float4*)(g_A + ((size_t)b * NPTS + j2) * COUT + g * 16);
#pragma unroll
        for (int q = 0; q < 4; ++q) {
            float4 v1 = ap1[q];
            float4 v2 = ap2[q];
            mx1[q * 4 + 0] = fmaxf(mx1[q * 4 + 0], v1.x);
            mx1[q * 4 + 1] = fmaxf(mx1[q * 4 + 1], v1.y);
            mx1[q * 4 + 2] = fmaxf(mx1[q * 4 + 2], v1.z);
            mx1[q * 4 + 3] = fmaxf(mx1[q * 4 + 3], v1.w);
            mx2[q * 4 + 0] = fmaxf(mx2[q * 4 + 0], v2.x);
            mx2[q * 4 + 1] = fmaxf(mx2[q * 4 + 1], v2.y);
            mx2[q * 4 + 2] = fmaxf(mx2[q * 4 + 2], v2.z);
            mx2[q * 4 + 3] = fmaxf(mx2[q * 4 + 3], v2.w);
        }
    }
    const float4* cp1 = (const float4*)(g_Cp + ((size_t)b * NPTS + n1) * COUT + g * 16);
    const float4* cp2 = (const float4*)(g_Cp + ((size_t)b * NPTS + n2) * COUT + g * 16);
    float* op1 = out + ((size_t)b * COUT + g * 16) * NPTS + n1;
    float* op2 = out + ((size_t)b * COUT + g * 16) * NPTS + n2;
#pragma unroll
    for (int q = 0; q < 4; ++q) {
        float4 c1 = cp1[q];
        float4 c2 = cp2[q];
        op1[(q * 4 + 0) * NPTS] = fmaxf(c1.x + mx1[q * 4 + 0], 0.f);
        op1[(q * 4 + 1) * NPTS] = fmaxf(c1.y + mx1[q * 4 + 1], 0.f);
        op1[(q * 4 + 2) * NPTS] = fmaxf(c1.z + mx1[q * 4 + 2], 0.f);
        op1[(q * 4 + 3) * NPTS] = fmaxf(c1.w + mx1[q * 4 + 3], 0.f);
        op2[(q * 4 + 0) * NPTS] = fmaxf(c2.x + mx2[q * 4 + 0], 0.f);
        op2[(q * 4 + 1) * NPTS] = fmaxf(c2.y + mx2[q * 4 + 1], 0.f);
        op2[(q * 4 + 2) * NPTS] = fmaxf(c2.z + mx2[q * 4 + 2], 0.f);
        op2[(q * 4 + 3) * NPTS] = fmaxf(c2.w + mx2[q * 4 + 3], 0.f);
    }
}

// ---------------- launch ----------------
extern "C" void kernel_launch(void* const* d_in, const int* in_sizes, int n_in,
                              void* d_out, int out_size) {
    const float *x = nullptr, *W1 = nullptr, *b1 = nullptr, *W2 = nullptr, *b2 = nullptr;
    for (int i = 0; i < n_in; ++i) {
        int s = in_sizes[i];
        const float* p = (const float*)d_in[i];
        if      (s == BATCH * CDIM * NPTS) x = p;
        else if (s == COUT * CDIM)        { if (!W1) W1 = p; else W2 = p; }
        else if (s == COUT)               { if (!b1) b1 = p; else b2 = p; }
    }
    float* out = (float*)d_out;
    (void)out_size;

    cudaFuncSetAttribute(knn_mma_kernel, cudaFuncAttributeMaxDynamicSharedMemorySize, KNN_SMEM);

    // knn placed 4th so the fixed ncu capture slot profiles it
    sq_kernel      <<<dim3(NPTS / 256, BATCH), 256>>>(x);
    tr_kernel      <<<dim3(NPTS / 32, CDIM / 32, BATCH), dim3(32, 8)>>>(x);
    feat_kernel    <<<dim3(NPTS / 64, BATCH), 256>>>(x, W1, b1, W2, b2);
    knn_mma_kernel <<<dim3(NPTS / 128, BATCH), 256, KNN_SMEM>>>();
    rescore_kernel <<<dim3(NPTS / 8, BATCH), 256>>>();
    gather_kernel  <<<dim3(NPTS / 128, BATCH), 256>>>(out);
}

// round 11
// speedup vs baseline: 2.8897x; 1.4307x over previous
#include <cuda_runtime.h>
#include <cuda_bf16.h>
#include <cstdint>

#define BATCH 8
#define CDIM  64
#define NPTS  4096
#define KNBR  16
#define COUT  64
#define KSUP  24          // candidate superset per row
#define LSTR  26          // smem list row stride (words)
#define NC    64          // candidates per tile in phase B
#define NTIL  (NPTS / NC) // 64

typedef unsigned long long ull;

// ---------------- scratch (no allocations allowed) ----------------
__device__ float          g_sq  [BATCH * NPTS];
__device__ int            g_idx [BATCH * NPTS * KNBR];
__device__ float          g_A   [BATCH * NPTS * COUT];
__device__ float          g_Cp  [BATCH * NPTS * COUT];
__device__ float          g_xt  [BATCH * NPTS * CDIM];   // point-major fp32
__device__ __nv_bfloat16  g_xh  [BATCH * NPTS * CDIM];   // point-major bf16
__device__ short          g_cand[BATCH * NPTS * KSUP];

// ---------------- helpers ----------------
__device__ __forceinline__ uint32_t smem_u32(const void* p) {
    uint32_t a;
    asm("{ .reg .u64 t; cvta.to.shared.u64 t, %1; cvt.u32.u64 %0, t; }" : "=r"(a) : "l"(p));
    return a;
}
__device__ __forceinline__ unsigned fsort(float v) {
    unsigned u = __float_as_uint(v);
    return u ^ (0x80000000u | (unsigned)((int)u >> 31));
}
__device__ __forceinline__ void ldmx4(uint32_t* r, uint32_t addr) {
    asm volatile("ldmatrix.sync.aligned.m8n8.x4.shared.b16 {%0,%1,%2,%3}, [%4];"
                 : "=r"(r[0]), "=r"(r[1]), "=r"(r[2]), "=r"(r[3]) : "r"(addr));
}
__device__ __forceinline__ void mma16816(float* c, const uint32_t* a, uint32_t b0, uint32_t b1) {
    asm volatile("mma.sync.aligned.m16n8k16.row.col.f32.bf16.bf16.f32 "
                 "{%0,%1,%2,%3}, {%4,%5,%6,%7}, {%8,%9}, {%0,%1,%2,%3};"
                 : "+f"(c[0]), "+f"(c[1]), "+f"(c[2]), "+f"(c[3])
                 : "r"(a[0]), "r"(a[1]), "r"(a[2]), "r"(a[3]), "r"(b0), "r"(b1));
}
__device__ __forceinline__ void cp16(uint32_t dst, const void* src) {
    asm volatile("cp.async.cg.shared.global [%0], [%1], 16;" :: "r"(dst), "l"(src));
}
// swizzled byte offset of 16B granule g (0..7) in row rr of a [rows][64bf16] tile
__device__ __forceinline__ int swz(int rr, int g) {
    return rr * 128 + ((g ^ (rr & 7)) << 4);
}

// ---------------- kernel 1: squared norms (exact fp32) ----------------
__global__ void sq_kernel(const float* __restrict__ x) {
    int b = blockIdx.y;
    int n = blockIdx.x * blockDim.x + threadIdx.x;
    const float* xp = x + (size_t)b * CDIM * NPTS + n;
    float s = 0.f;
#pragma unroll
    for (int c = 0; c < CDIM; ++c) { float v = xp[c * NPTS]; s = fmaf(v, v, s); }
    g_sq[b * NPTS + n] = s;
}

// ---------------- kernel 1b: transpose to point-major fp32 + bf16 ----------------
__global__ void tr_kernel(const float* __restrict__ x) {
    __shared__ float tile[32][33];
    const int tx = threadIdx.x, ty = threadIdx.y;
    const int n0 = blockIdx.x * 32, c0 = blockIdx.y * 32, b = blockIdx.z;
    const float* xb = x + (size_t)b * CDIM * NPTS;
#pragma unroll
    for (int i = 0; i < 4; ++i)
        tile[ty + i * 8][tx] = xb[(c0 + ty + i * 8) * NPTS + n0 + tx];
    __syncthreads();
#pragma unroll
    for (int i = 0; i < 4; ++i) {
        int n = n0 + ty + i * 8, c = c0 + tx;
        float v = tile[tx][ty + i * 8];
        size_t o = ((size_t)b * NPTS + n) * CDIM + c;
        g_xt[o] = v;
        g_xh[o] = __float2bfloat16(v);
    }
}

// ---------------- kernel 2: HMMA approx distances + top-24 superset ----------------
// Keys are raw fp32 bits of (approx d^2 >= 0): order-monotone, no fsort.
// key = (bits & 0xFFFFF000) | idx12.  Top-24 list lives in smem (dynamic-index
// insert = 1 STS); rescan packs slot into low 5 bits and max-reduces via IMNMX.
#define SM_A    0                           // 16384
#define SM_B0   16384                       // 8192
#define SM_B1   24576                       // 8192
#define SM_SQ   32768                       // float[2][64]  = 512
#define SM_THR  33280                       // float[128]    = 512
#define SM_CNT  33792                       // int[4][128]   = 2048
#define SM_PEND 35840                       // u32[4][16][128] = 32768
#define SM_LIST 68608                       // u32[128][LSTR]  = 13312
#define KNN_SMEM (SM_LIST + 128 * LSTR * 4) // 81920

__global__ __launch_bounds__(256, 2) void knn_mma_kernel() {
    extern __shared__ char sm[];
    float*    sqb  = (float*)   (sm + SM_SQ);
    float*    thr  = (float*)   (sm + SM_THR);
    int*      cnt  = (int*)     (sm + SM_CNT);
    unsigned* pend = (unsigned*)(sm + SM_PEND);
    unsigned* list = (unsigned*)(sm + SM_LIST);

    const int tid  = threadIdx.x;
    const int w    = tid >> 5;
    const int lane = tid & 31;
    const int b    = blockIdx.y;
    const int row0 = blockIdx.x * 128;
    const uint32_t smb = smem_u32(sm);

    const __nv_bfloat16* gb = g_xh + (size_t)b * NPTS * CDIM;

    // prologue: A tile (swizzled), B tile 0, sq slice 0, thr, list init
#pragma unroll
    for (int i = 0; i < 4; ++i) {    // A: 1024 uint4
        int q = tid + i * 256, rr = q >> 3, g = q & 7;
        *(uint4*)(sm + SM_A + swz(rr, g)) = *(const uint4*)(gb + (size_t)(row0 + rr) * CDIM + g * 8);
    }
#pragma unroll
    for (int i = 0; i < 2; ++i) {    // B0: 512 uint4 (64 rows)
        int q = tid + i * 256, rr = q >> 3, g = q & 7;
        *(uint4*)(sm + SM_B0 + swz(rr, g)) = *(const uint4*)(gb + (size_t)rr * CDIM + g * 8);
    }
    if (tid < 16)
        *(float4*)(sqb + tid * 4) = *(const float4*)(g_sq + (size_t)b * NPTS + tid * 4);
    if (tid < 128) thr[tid] = 3.4e38f;
    for (int i = tid; i < 128 * LSTR; i += 256) list[i] = 0xFFFFFFFFu;
    __syncthreads();

    // GEMM role (all 8 warps): rows wrow..wrow+15
    const int wrow = w * 16;
    const int arow = wrow + (lane & 7) + ((lane >> 3) & 1) * 8;
    const int rA   = wrow + (lane >> 2);
    const int rB   = rA + 8;
    const int seg  = lane & 3;
    const int mloc = seg * 2;
    const float sqnA = g_sq[(size_t)b * NPTS + row0 + rA];
    const float sqnB = g_sq[(size_t)b * NPTS + row0 + rB];

    // A fragments: block-constant, load once
    uint32_t af[4][4];
#pragma unroll
    for (int kc = 0; kc < 4; ++kc) {
        int ach = kc * 2 + (lane >> 4);
        ldmx4(af[kc], smb + SM_A + swz(arow, ach));
    }

    // selection state (threads 0..127 own row = row0 + tid); list in smem
    unsigned worstm = 0xFFFFFFFFu;   // slot-mangled max of list (top-27 bits valid)
    int wpos = 0;

    for (int t = 0; t < NTIL; ++t) {
        const uint32_t bbase = smb + ((t & 1) ? SM_B1 : SM_B0);
        const float*   sql   = sqb + (t & 1) * 64;
        const float thrA = thr[rA];
        const float thrB = thr[rB];
        const int   tb   = t * NC;
        int cA = 0, cB = 0;   // register counters; <=16 by construction

#pragma unroll
        for (int nf = 0; nf < 8; ++nf) {
            int brow = nf * 8 + (lane & 7);
            int bg   = lane >> 3;
            uint32_t p[4], q4[4];
            ldmx4(p,  bbase + swz(brow, bg));
            ldmx4(q4, bbase + swz(brow, bg + 4));
            float acc[4] = {0.f, 0.f, 0.f, 0.f};
            mma16816(acc, af[0], p[0],  p[1]);
            mma16816(acc, af[1], p[2],  p[3]);
            mma16816(acc, af[2], q4[0], q4[1]);
            mma16816(acc, af[3], q4[2], q4[3]);

            // fused epilogue: v = sq[m] + sq[n] - 2*dot = approx d^2 >= 0
            int    ml = mloc + nf * 8;
            float2 ss = *(const float2*)(sql + ml);
            int    m0 = tb + ml;
            float sA0 = ss.x + sqnA, sA1 = ss.y + sqnA;
            float sB0 = ss.x + sqnB, sB1 = ss.y + sqnB;
            float v00 = fmaf(-2.f, acc[0], sA0);
            float v01 = fmaf(-2.f, acc[1], sA1);
            float v10 = fmaf(-2.f, acc[2], sB0);
            float v11 = fmaf(-2.f, acc[3], sB1);
            if (v00 <= thrA) pend[(seg * 16 + cA++) * 128 + rA] = (__float_as_uint(v00) & 0xFFFFF000u) | (unsigned)m0;
            if (v01 <= thrA) pend[(seg * 16 + cA++) * 128 + rA] = (__float_as_uint(v01) & 0xFFFFF000u) | (unsigned)(m0 + 1);
            if (v10 <= thrB) pend[(seg * 16 + cB++) * 128 + rB] = (__float_as_uint(v10) & 0xFFFFF000u) | (unsigned)m0;
            if (v11 <= thrB) pend[(seg * 16 + cB++) * 128 + rB] = (__float_as_uint(v11) & 0xFFFFF000u) | (unsigned)(m0 + 1);
        }
        cnt[seg * 128 + rA] = cA;
        cnt[seg * 128 + rB] = cB;
        __syncthreads();   // pend + cnt visible

        if (tid < 128) {
            unsigned* lrow = list + tid * LSTR;
#pragma unroll
            for (int sg = 0; sg < 4; ++sg) {
                unsigned myc  = (unsigned)cnt[sg * 128 + tid];
                unsigned cmax = __reduce_max_sync(0xffffffffu, myc);
                for (unsigned j = 0; j < cmax; ++j) {
                    unsigned kn = (j < myc) ? pend[(sg * 16 + (int)j) * 128 + tid] : 0xFFFFFFFFu;
                    bool take = kn < worstm;
                    if (__any_sync(0xffffffffu, take)) {
                        if (take) lrow[wpos] = kn;           // 1 STS, dynamic slot
                        // rescan: slot-packed max via IMNMX
                        unsigned m = 0;
#pragma unroll
                        for (int s = 0; s < KSUP; s += 2) {
                            uint2 two = *(const uint2*)(lrow + s);
                            unsigned t0 = (two.x & 0xFFFFFFE0u) | (unsigned)s;
                            unsigned t1 = (two.y & 0xFFFFFFE0u) | (unsigned)(s + 1);
                            unsigned mx = t0 > t1 ? t0 : t1;
                            m = m > mx ? m : mx;
                        }
                        worstm = m;
                        wpos = (int)(m & 31u);
                    }
                }
            }
            thr[tid] = __uint_as_float(worstm | 0xFFFu);
        } else if (t + 1 < NTIL) {
            // warps 4-7: async prefetch next B tile + sq slice
            const int t2 = tid - 128;
            uint32_t dstb = smb + (((t + 1) & 1) ? SM_B1 : SM_B0);
            const __nv_bfloat16* src = gb + (size_t)(t + 1) * NC * CDIM;
#pragma unroll
            for (int i = 0; i < 4; ++i) {
                int q = t2 + i * 128, rr = q >> 3, g = q & 7;
                cp16(dstb + swz(rr, g), src + (size_t)rr * CDIM + g * 8);
            }
            if (t2 < 16)
                cp16(smb + SM_SQ + (((t + 1) & 1) * 64 + t2 * 4) * 4,
                     g_sq + (size_t)b * NPTS + (t + 1) * NC + t2 * 4);
            asm volatile("cp.async.commit_group;");
            asm volatile("cp.async.wait_group 0;");
        }
        __syncthreads();   // flush done (thr updated), B(t+1) ready, pend reusable
    }

    if (tid < 128) {
        short* op = g_cand + ((size_t)b * NPTS + row0 + tid) * KSUP;
        const unsigned* lrow = list + tid * LSTR;
#pragma unroll
        for (int k = 0; k < KSUP; ++k) op[k] = (short)(lrow[k] & 0xFFFu);
    }
}

// ---------------- kernel 2b: exact rescore (coalesced), top-16 ----------------
__global__ __launch_bounds__(256) void rescore_kernel() {
    __shared__ float xrow[8][CDIM];
    __shared__ float dots[8][KSUP];
    const int lane = threadIdx.x & 31;
    const int w    = threadIdx.x >> 5;
    const int b    = blockIdx.y;
    const int n    = blockIdx.x * 8 + w;
    const size_t rb = (size_t)b * NPTS + n;

    *(float2*)(&xrow[w][lane * 2]) = *(const float2*)(g_xt + rb * CDIM + lane * 2);
    __syncwarp();

    const short* cp = g_cand + rb * KSUP;
    const float* xseg = &xrow[w][(lane & 3) * 16];

    // 3 groups of 8 candidates; 4 lanes per candidate (coalesced 256B rows)
#pragma unroll
    for (int g = 0; g < 3; ++g) {
        int c = g * 8 + (lane >> 2);
        int j = (int)cp[c];
        const float* yp = g_xt + ((size_t)b * NPTS + j) * CDIM + (lane & 3) * 16;
        float d = 0.f;
#pragma unroll
        for (int q = 0; q < 4; ++q) {
            float4 yv = *(const float4*)(yp + q * 4);
            float4 xv = *(const float4*)(xseg + q * 4);
            d = fmaf(xv.x, yv.x, d);
            d = fmaf(xv.y, yv.y, d);
            d = fmaf(xv.z, yv.z, d);
            d = fmaf(xv.w, yv.w, d);
        }
        d += __shfl_xor_sync(0xffffffffu, d, 1);
        d += __shfl_xor_sync(0xffffffffu, d, 2);
        if ((lane & 3) == 0) dots[w][c] = d;
    }
    __syncwarp();

    ull key = ~0ULL;
    if (lane < KSUP) {
        int j = (int)cp[lane];
        if (j != n) {
            float dist = fmaf(-2.f, dots[w][lane], g_sq[(size_t)b * NPTS + j]);
            key = ((ull)fsort(dist) << 32) | (unsigned)j;
        }
    }
#pragma unroll
    for (int k = 2; k <= 32; k <<= 1) {
#pragma unroll
        for (int jj = k >> 1; jj > 0; jj >>= 1) {
            ull other = __shfl_xor_sync(0xffffffffu, key, jj);
            bool up   = ((lane & k) == 0);
            bool low  = ((lane & jj) == 0);
            bool keep_small = (low == up);
            ull mn = key < other ? key : other;
            ull mx = key < other ? other : key;
            key = keep_small ? mn : mx;
        }
    }
    if (lane < KNBR)
        g_idx[rb * KNBR + lane] = (int)(key & 0xFFFFu);
}

// ---------------- kernel 3: A = W1.x ; Cpre = (W2-W1).x + b1+b2 ----------------
__global__ void feat_kernel(const float* __restrict__ x,
                            const float* __restrict__ W1, const float* __restrict__ b1,
                            const float* __restrict__ W2, const float* __restrict__ b2) {
    __shared__ float xs [CDIM][64];
    __shared__ float w1s[COUT][CDIM];
    __shared__ float wds[COUT][CDIM];
    __shared__ float bs [COUT];

    const int tid = threadIdx.x;
    const int b   = blockIdx.y;
    const int n0  = blockIdx.x * 64;
    const float* xb = x + (size_t)b * CDIM * NPTS;

#pragma unroll
    for (int i = 0; i < 4; ++i) {
        int q = tid + i * 256, c = q >> 4, mg = q & 15;
        *(float4*)(&xs[c][mg * 4]) = *(const float4*)(xb + c * NPTS + n0 + mg * 4);
    }
#pragma unroll
    for (int i = 0; i < 4; ++i) {
        int q = tid + i * 256, o = q >> 4, cg = (q & 15) * 4;
        float4 w1v = *(const float4*)(W1 + o * CDIM + cg);
        float4 w2v = *(const float4*)(W2 + o * CDIM + cg);
        *(float4*)(&w1s[o][cg]) = w1v;
        *(float4*)(&wds[o][cg]) = make_float4(w2v.x - w1v.x, w2v.y - w1v.y,
                                              w2v.z - w1v.z, w2v.w - w1v.w);
    }
    if (tid < COUT) bs[tid] = b1[tid] + b2[tid];
    __syncthreads();

    const int tx = tid & 15;
    const int ty = tid >> 4;
    float aA[4][4] = {}, aC[4][4] = {};
#pragma unroll 16
    for (int c = 0; c < CDIM; ++c) {
        float4 xv = *(const float4*)(&xs[c][tx * 4]);
        float xr[4] = { xv.x, xv.y, xv.z, xv.w };
#pragma unroll
        for (int jj = 0; jj < 4; ++jj) {
            float w1e = w1s[ty * 4 + jj][c];
            float wde = wds[ty * 4 + jj][c];
#pragma unroll
            for (int i = 0; i < 4; ++i) {
                aA[i][jj] = fmaf(xr[i], w1e, aA[i][jj]);
                aC[i][jj] = fmaf(xr[i], wde, aC[i][jj]);
            }
        }
    }
#pragma unroll
    for (int i = 0; i < 4; ++i) {
        int n = n0 + tx * 4 + i;
        float* ap = g_A  + ((size_t)b * NPTS + n) * COUT + ty * 4;
        float* cp = g_Cp + ((size_t)b * NPTS + n) * COUT + ty * 4;
        *(float4*)ap = make_float4(aA[i][0], aA[i][1], aA[i][2], aA[i][3]);
        *(float4*)cp = make_float4(aC[i][0] + bs[ty * 4 + 0],
                                   aC[i][1] + bs[ty * 4 + 1],
                                   aC[i][2] + bs[ty * 4 + 2],
                                   aC[i][3] + bs[ty * 4 + 3]);
    }
}

// ---------------- kernel 4: gather-max + relu (2 points/thread ILP) ----------------
__global__ __launch_bounds__(256) void gather_kernel(float* __restrict__ out) {
    const int tid = threadIdx.x;
    const int b   = blockIdx.y;
    const int l   = tid & 63;
    const int g   = tid >> 6;
    const int n1  = blockIdx.x * 128 + l;
    const int n2  = n1 + 64;
    const int* ip1 = g_idx + ((size_t)b * NPTS + n1) * KNBR;
    const int* ip2 = g_idx + ((size_t)b * NPTS + n2) * KNBR;

    float mx1[16], mx2[16];
#pragma unroll
    for (int i = 0; i < 16; ++i) { mx1[i] = -3.4e38f; mx2[i] = -3.4e38f; }

#pragma unroll
    for (int k = 0; k < KNBR; ++k) {
        int j1 = ip1[k], j2 = ip2[k];
        const float4* ap1 = (const float4*)(g_A + ((size_t)b * NPTS + j1) * COUT + g * 16);
        const float4* ap2 = (const float4*)(g_A + ((size_t)b * NPTS + j2) * COUT + g * 16);
#pragma unroll
        for (int q = 0; q < 4; ++q) {
            float4 v1 = ap1[q];
            float4 v2 = ap2[q];
            mx1[q * 4 + 0] = fmaxf(mx1[q * 4 + 0], v1.x);
            mx1[q * 4 + 1] = fmaxf(mx1[q * 4 + 1], v1.y);
            mx1[q * 4 + 2] = fmaxf(mx1[q * 4 + 2], v1.z);
            mx1[q * 4 + 3] = fmaxf(mx1[q * 4 + 3], v1.w);
            mx2[q * 4 + 0] = fmaxf(mx2[q * 4 + 0], v2.x);
            mx2[q * 4 + 1] = fmaxf(mx2[q * 4 + 1], v2.y);
            mx2[q * 4 + 2] = fmaxf(mx2[q * 4 + 2], v2.z);
            mx2[q * 4 + 3] = fmaxf(mx2[q * 4 + 3], v2.w);
        }
    }
    const float4* cp1 = (const float4*)(g_Cp + ((size_t)b * NPTS + n1) * COUT + g * 16);
    const float4* cp2 = (const float4*)(g_Cp + ((size_t)b * NPTS + n2) * COUT + g * 16);
    float* op1 = out + ((size_t)b * COUT + g * 16) * NPTS + n1;
    float* op2 = out + ((size_t)b * COUT + g * 16) * NPTS + n2;
#pragma unroll
    for (int q = 0; q < 4; ++q) {
        float4 c1 = cp1[q];
        float4 c2 = cp2[q];
        op1[(q * 4 + 0) * NPTS] = fmaxf(c1.x + mx1[q * 4 + 0], 0.f);
        op1[(q * 4 + 1) * NPTS] = fmaxf(c1.y + mx1[q * 4 + 1], 0.f);
        op1[(q * 4 + 2) * NPTS] = fmaxf(c1.z + mx1[q * 4 + 2], 0.f);
        op1[(q * 4 + 3) * NPTS] = fmaxf(c1.w + mx1[q * 4 + 3], 0.f);
        op2[(q * 4 + 0) * NPTS] = fmaxf(c2.x + mx2[q * 4 + 0], 0.f);
        op2[(q * 4 + 1) * NPTS] = fmaxf(c2.y + mx2[q * 4 + 1], 0.f);
        op2[(q * 4 + 2) * NPTS] = fmaxf(c2.z + mx2[q * 4 + 2], 0.f);
        op2[(q * 4 + 3) * NPTS] = fmaxf(c2.w + mx2[q * 4 + 3], 0.f);
    }
}

// ---------------- launch ----------------
extern "C" void kernel_launch(void* const* d_in, const int* in_sizes, int n_in,
                              void* d_out, int out_size) {
    const float *x = nullptr, *W1 = nullptr, *b1 = nullptr, *W2 = nullptr, *b2 = nullptr;
    for (int i = 0; i < n_in; ++i) {
        int s = in_sizes[i];
        const float* p = (const float*)d_in[i];
        if      (s == BATCH * CDIM * NPTS) x = p;
        else if (s == COUT * CDIM)        { if (!W1) W1 = p; else W2 = p; }
        else if (s == COUT)               { if (!b1) b1 = p; else b2 = p; }
    }
    float* out = (float*)d_out;
    (void)out_size;

    cudaFuncSetAttribute(knn_mma_kernel, cudaFuncAttributeMaxDynamicSharedMemorySize, KNN_SMEM);

    // knn placed 4th so the fixed ncu capture slot profiles it
    sq_kernel      <<<dim3(NPTS / 256, BATCH), 256>>>(x);
    tr_kernel      <<<dim3(NPTS / 32, CDIM / 32, BATCH), dim3(32, 8)>>>(x);
    feat_kernel    <<<dim3(NPTS / 64, BATCH), 256>>>(x, W1, b1, W2, b2);
    knn_mma_kernel <<<dim3(NPTS / 128, BATCH), 256, KNN_SMEM>>>();
    rescore_kernel <<<dim3(NPTS / 8, BATCH), 256>>>();
    gather_kernel  <<<dim3(NPTS / 128, BATCH), 256>>>(out);
}

// round 13
// speedup vs baseline: 2.9355x; 1.0159x over previous
#include <cuda_runtime.h>
#include <cuda_bf16.h>
#include <cstdint>

#define BATCH 8
#define CDIM  64
#define NPTS  4096
#define KNBR  16
#define COUT  64
#define KSUP  24          // candidate superset per row
#define LSTR  26          // smem list row stride (words, EVEN: keeps LDS.64 aligned)
#define NC    64          // candidates per tile in phase B
#define NTIL  (NPTS / NC) // 64
#define COFF  512.0f      // row-order-preserving positive offset

typedef unsigned long long ull;

// ---------------- scratch (no allocations allowed) ----------------
__device__ float          g_sq  [BATCH * NPTS];
__device__ float          g_sqC [BATCH * NPTS];          // sq + COFF
__device__ int            g_idx [BATCH * NPTS * KNBR];
__device__ float          g_A   [BATCH * NPTS * COUT];
__device__ float          g_Cp  [BATCH * NPTS * COUT];
__device__ float          g_xt  [BATCH * NPTS * CDIM];   // point-major fp32
__device__ __nv_bfloat16  g_xh  [BATCH * NPTS * CDIM];   // point-major bf16
__device__ short          g_cand[BATCH * NPTS * KSUP];

// ---------------- helpers ----------------
__device__ __forceinline__ uint32_t smem_u32(const void* p) {
    uint32_t a;
    asm("{ .reg .u64 t; cvta.to.shared.u64 t, %1; cvt.u32.u64 %0, t; }" : "=r"(a) : "l"(p));
    return a;
}
__device__ __forceinline__ unsigned fsort(float v) {
    unsigned u = __float_as_uint(v);
    return u ^ (0x80000000u | (unsigned)((int)u >> 31));
}
__device__ __forceinline__ void ldmx4(uint32_t* r, uint32_t addr) {
    asm volatile("ldmatrix.sync.aligned.m8n8.x4.shared.b16 {%0,%1,%2,%3}, [%4];"
                 : "=r"(r[0]), "=r"(r[1]), "=r"(r[2]), "=r"(r[3]) : "r"(addr));
}
__device__ __forceinline__ void mma16816(float* c, const uint32_t* a, uint32_t b0, uint32_t b1) {
    asm volatile("mma.sync.aligned.m16n8k16.row.col.f32.bf16.bf16.f32 "
                 "{%0,%1,%2,%3}, {%4,%5,%6,%7}, {%8,%9}, {%0,%1,%2,%3};"
                 : "+f"(c[0]), "+f"(c[1]), "+f"(c[2]), "+f"(c[3])
                 : "r"(a[0]), "r"(a[1]), "r"(a[2]), "r"(a[3]), "r"(b0), "r"(b1));
}
// swizzled byte offset of 16B granule g (0..7) in row rr of a [rows][64bf16] tile
__device__ __forceinline__ int swz(int rr, int g) {
    return rr * 128 + ((g ^ (rr & 7)) << 4);
}

// ---------------- kernel 1: squared norms (exact fp32) ----------------
__global__ void sq_kernel(const float* __restrict__ x) {
    int b = blockIdx.y;
    int n = blockIdx.x * blockDim.x + threadIdx.x;
    const float* xp = x + (size_t)b * CDIM * NPTS + n;
    float s = 0.f;
#pragma unroll
    for (int c = 0; c < CDIM; ++c) { float v = xp[c * NPTS]; s = fmaf(v, v, s); }
    g_sq [b * NPTS + n] = s;
    g_sqC[b * NPTS + n] = s + COFF;
}

// ---------------- kernel 1b: transpose to point-major fp32 + bf16 ----------------
__global__ void tr_kernel(const float* __restrict__ x) {
    __shared__ float tile[32][33];
    const int tx = threadIdx.x, ty = threadIdx.y;
    const int n0 = blockIdx.x * 32, c0 = blockIdx.y * 32, b = blockIdx.z;
    const float* xb = x + (size_t)b * CDIM * NPTS;
#pragma unroll
    for (int i = 0; i < 4; ++i)
        tile[ty + i * 8][tx] = xb[(c0 + ty + i * 8) * NPTS + n0 + tx];
    __syncthreads();
#pragma unroll
    for (int i = 0; i < 4; ++i) {
        int n = n0 + ty + i * 8, c = c0 + tx;
        float v = tile[tx][ty + i * 8];
        size_t o = ((size_t)b * NPTS + n) * CDIM + c;
        g_xt[o] = v;
        g_xh[o] = __float2bfloat16(v);
    }
}

// ---------------- kernel 2: HMMA approx distances + top-24 superset ----------------
// Keys: raw fp32 bits of v = sqC[m] - 2*dot (> 0, per-row order == d^2 order).
// key = (bits & 0xFFFFF000) | idx12. Single B buffer; warps 4-7 stage B(t+1)
// through registers across the flush barrier. 3 blocks/SM.
#define SM_A    0                            // 16384
#define SM_B0   16384                        // 8192
#define SM_SQ   24576                        // float[64] = 256
#define SM_THR  24832                        // float[128] = 512
#define SM_CNT  25344                        // int[4][128] = 2048
#define SM_PEND 27392                        // u32[4][16][128] = 32768
#define SM_LIST 60160                        // u32[128][LSTR] = 13312
#define KNN_SMEM (SM_LIST + 128 * LSTR * 4)  // 73472

__global__ __launch_bounds__(256, 3) void knn_mma_kernel() {
    extern __shared__ char sm[];
    float*    sqb  = (float*)   (sm + SM_SQ);
    float*    thr  = (float*)   (sm + SM_THR);
    int*      cnt  = (int*)     (sm + SM_CNT);
    unsigned* pend = (unsigned*)(sm + SM_PEND);
    unsigned* list = (unsigned*)(sm + SM_LIST);

    const int tid  = threadIdx.x;
    const int w    = tid >> 5;
    const int lane = tid & 31;
    const int b    = blockIdx.y;
    const int row0 = blockIdx.x * 128;
    const uint32_t smb = smem_u32(sm);

    const __nv_bfloat16* gb = g_xh + (size_t)b * NPTS * CDIM;

    // prologue: A tile (swizzled), B tile 0, sqC slice 0, thr, list init
#pragma unroll
    for (int i = 0; i < 4; ++i) {    // A: 1024 uint4
        int q = tid + i * 256, rr = q >> 3, g = q & 7;
        *(uint4*)(sm + SM_A + swz(rr, g)) = *(const uint4*)(gb + (size_t)(row0 + rr) * CDIM + g * 8);
    }
#pragma unroll
    for (int i = 0; i < 2; ++i) {    // B0: 512 uint4 (64 rows)
        int q = tid + i * 256, rr = q >> 3, g = q & 7;
        *(uint4*)(sm + SM_B0 + swz(rr, g)) = *(const uint4*)(gb + (size_t)rr * CDIM + g * 8);
    }
    if (tid < 16)
        *(float4*)(sqb + tid * 4) = *(const float4*)(g_sqC + (size_t)b * NPTS + tid * 4);
    if (tid < 128) thr[tid] = 3.4e38f;
    for (int i = tid; i < 128 * LSTR; i += 256) list[i] = 0xFFFFFFFFu;
    __syncthreads();

    // GEMM role (all 8 warps): rows wrow..wrow+15
    const int wrow = w * 16;
    const int arow = wrow + (lane & 7) + ((lane >> 3) & 1) * 8;
    const int rA   = wrow + (lane >> 2);
    const int rB   = rA + 8;
    const int seg  = lane & 3;
    const int mloc = seg * 2;
    const int t2   = tid - 128;

    // A fragments: block-constant, load once
    uint32_t af[4][4];
#pragma unroll
    for (int kc = 0; kc < 4; ++kc) {
        int ach = kc * 2 + (lane >> 4);
        ldmx4(af[kc], smb + SM_A + swz(arow, ach));
    }

    // selection state (threads 0..127 own row = row0 + tid); list in smem
    unsigned worstm = 0xFFFFFFFFu;   // slot-mangled max of list (top-27 bits valid)
    int wpos = 0;

    for (int t = 0; t < NTIL; ++t) {
        const float thrA = thr[rA];
        const float thrB = thr[rB];
        const int   tb   = t * NC;
        int cA = 0, cB = 0;   // register counters; <=16 by construction

#pragma unroll
        for (int nf = 0; nf < 8; ++nf) {
            int brow = nf * 8 + (lane & 7);
            int bg   = lane >> 3;
            uint32_t p[4], q4[4];
            ldmx4(p,  smb + SM_B0 + swz(brow, bg));
            ldmx4(q4, smb + SM_B0 + swz(brow, bg + 4));
            float acc[4] = {0.f, 0.f, 0.f, 0.f};
            mma16816(acc, af[0], p[0],  p[1]);
            mma16816(acc, af[1], p[2],  p[3]);
            mma16816(acc, af[2], q4[0], q4[1]);
            mma16816(acc, af[3], q4[2], q4[3]);

            // fused epilogue: v = sqC[m] - 2*dot  (>0; per-row order == d^2)
            int    ml = mloc + nf * 8;
            float2 ss = *(const float2*)(sqb + ml);
            int    m0 = tb + ml;
            float v00 = fmaf(-2.f, acc[0], ss.x);
            float v01 = fmaf(-2.f, acc[1], ss.y);
            float v10 = fmaf(-2.f, acc[2], ss.x);
            float v11 = fmaf(-2.f, acc[3], ss.y);
            if (v00 <= thrA) pend[(seg * 16 + cA++) * 128 + rA] = (__float_as_uint(v00) & 0xFFFFF000u) | (unsigned)m0;
            if (v01 <= thrA) pend[(seg * 16 + cA++) * 128 + rA] = (__float_as_uint(v01) & 0xFFFFF000u) | (unsigned)(m0 + 1);
            if (v10 <= thrB) pend[(seg * 16 + cB++) * 128 + rB] = (__float_as_uint(v10) & 0xFFFFF000u) | (unsigned)m0;
            if (v11 <= thrB) pend[(seg * 16 + cB++) * 128 + rB] = (__float_as_uint(v11) & 0xFFFFF000u) | (unsigned)(m0 + 1);
        }
        cnt[seg * 128 + rA] = cA;
        cnt[seg * 128 + rB] = cB;

        // warps 4-7: stage first half of B(t+1) + sqC(t+1) into registers
        uint4 st0, st1; float sqv = 0.f;
        if (tid >= 128 && t + 1 < NTIL) {
            const __nv_bfloat16* src = gb + (size_t)(t + 1) * NC * CDIM;
            { int q = t2,       rr = q >> 3, g = q & 7; st0 = *(const uint4*)(src + (size_t)rr * CDIM + g * 8); }
            { int q = t2 + 128, rr = q >> 3, g = q & 7; st1 = *(const uint4*)(src + (size_t)rr * CDIM + g * 8); }
            if (t2 < 64) sqv = g_sqC[(size_t)b * NPTS + (t + 1) * NC + t2];
        }
        __syncthreads();   // pend + cnt visible; B(t) fully consumed

        if (tid < 128) {
            unsigned* lrow = list + tid * LSTR;
#pragma unroll
            for (int sg = 0; sg < 4; ++sg) {
                unsigned myc  = (unsigned)cnt[sg * 128 + tid];
                unsigned cmax = __reduce_max_sync(0xffffffffu, myc);
                for (unsigned j = 0; j < cmax; ++j) {
                    unsigned kn = (j < myc) ? pend[(sg * 16 + (int)j) * 128 + tid] : 0xFFFFFFFFu;
                    bool take = kn < worstm;
                    if (__any_sync(0xffffffffu, take)) {
                        if (take) lrow[wpos] = kn;           // 1 STS, dynamic slot
                        // rescan: slot-packed max via IMNMX
                        unsigned m = 0;
#pragma unroll
                        for (int s = 0; s < KSUP; s += 2) {
                            uint2 two = *(const uint2*)(lrow + s);
                            unsigned t0 = (two.x & 0xFFFFFFE0u) | (unsigned)s;
                            unsigned t1 = (two.y & 0xFFFFFFE0u) | (unsigned)(s + 1);
                            unsigned mx = t0 > t1 ? t0 : t1;
                            m = m > mx ? m : mx;
                        }
                        worstm = m;
                        wpos = (int)(m & 31u);
                    }
                }
            }
            thr[tid] = __uint_as_float(worstm | 0xFFFu);
        } else if (t + 1 < NTIL) {
            // warps 4-7: store staged half, then load+store second half
            const __nv_bfloat16* src = gb + (size_t)(t + 1) * NC * CDIM;
            { int q = t2,       rr = q >> 3, g = q & 7; *(uint4*)(sm + SM_B0 + swz(rr, g)) = st0; }
            { int q = t2 + 128, rr = q >> 3, g = q & 7; *(uint4*)(sm + SM_B0 + swz(rr, g)) = st1; }
            { int q = t2 + 256, rr = q >> 3, g = q & 7;
              *(uint4*)(sm + SM_B0 + swz(rr, g)) = *(const uint4*)(src + (size_t)rr * CDIM + g * 8); }
            { int q = t2 + 384, rr = q >> 3, g = q & 7;
              *(uint4*)(sm + SM_B0 + swz(rr, g)) = *(const uint4*)(src + (size_t)rr * CDIM + g * 8); }
            if (t2 < 64) sqb[t2] = sqv;
        }
        __syncthreads();   // flush done (thr updated), B(t+1) ready, pend reusable
    }

    if (tid < 128) {
        short* op = g_cand + ((size_t)b * NPTS + row0 + tid) * KSUP;
        const unsigned* lrow = list + tid * LSTR;
#pragma unroll
        for (int k = 0; k < KSUP; ++k) op[k] = (short)(lrow[k] & 0xFFFu);
    }
}

// ---------------- kernel 2b: exact rescore (coalesced), top-16 ----------------
__global__ __launch_bounds__(256) void rescore_kernel() {
    __shared__ float xrow[8][CDIM];
    __shared__ float dots[8][KSUP];
    const int lane = threadIdx.x & 31;
    const int w    = threadIdx.x >> 5;
    const int b    = blockIdx.y;
    const int n    = blockIdx.x * 8 + w;
    const size_t rb = (size_t)b * NPTS + n;

    *(float2*)(&xrow[w][lane * 2]) = *(const float2*)(g_xt + rb * CDIM + lane * 2);
    __syncwarp();

    const short* cp = g_cand + rb * KSUP;
    const float* xseg = &xrow[w][(lane & 3) * 16];

    // 3 groups of 8 candidates; 4 lanes per candidate (coalesced 256B rows)
#pragma unroll
    for (int g = 0; g < 3; ++g) {
        int c = g * 8 + (lane >> 2);
        int j = (int)cp[c];
        const float* yp = g_xt + ((size_t)b * NPTS + j) * CDIM + (lane & 3) * 16;
        float d = 0.f;
#pragma unroll
        for (int q = 0; q < 4; ++q) {
            float4 yv = *(const float4*)(yp + q * 4);
            float4 xv = *(const float4*)(xseg + q * 4);
            d = fmaf(xv.x, yv.x, d);
            d = fmaf(xv.y, yv.y, d);
            d = fmaf(xv.z, yv.z, d);
            d = fmaf(xv.w, yv.w, d);
        }
        d += __shfl_xor_sync(0xffffffffu, d, 1);
        d += __shfl_xor_sync(0xffffffffu, d, 2);
        if ((lane & 3) == 0) dots[w][c] = d;
    }
    __syncwarp();

    ull key = ~0ULL;
    if (lane < KSUP) {
        int j = (int)cp[lane];
        if (j != n) {
            float dist = fmaf(-2.f, dots[w][lane], g_sq[(size_t)b * NPTS + j]);
            key = ((ull)fsort(dist) << 32) | (unsigned)j;
        }
    }
#pragma unroll
    for (int k = 2; k <= 32; k <<= 1) {
#pragma unroll
        for (int jj = k >> 1; jj > 0; jj >>= 1) {
            ull other = __shfl_xor_sync(0xffffffffu, key, jj);
            bool up   = ((lane & k) == 0);
            bool low  = ((lane & jj) == 0);
            bool keep_small = (low == up);
            ull mn = key < other ? key : other;
            ull mx = key < other ? other : key;
            key = keep_small ? mn : mx;
        }
    }
    if (lane < KNBR)
        g_idx[rb * KNBR + lane] = (int)(key & 0xFFFFu);
}

// ---------------- kernel 3: A = W1.x ; Cpre = (W2-W1).x + b1+b2 ----------------
__global__ void feat_kernel(const float* __restrict__ x,
                            const float* __restrict__ W1, const float* __restrict__ b1,
                            const float* __restrict__ W2, const float* __restrict__ b2) {
    __shared__ float xs [CDIM][64];
    __shared__ float w1s[COUT][CDIM];
    __shared__ float wds[COUT][CDIM];
    __shared__ float bs [COUT];

    const int tid = threadIdx.x;
    const int b   = blockIdx.y;
    const int n0  = blockIdx.x * 64;
    const float* xb = x + (size_t)b * CDIM * NPTS;

#pragma unroll
    for (int i = 0; i < 4; ++i) {
        int q = tid + i * 256, c = q >> 4, mg = q & 15;
        *(float4*)(&xs[c][mg * 4]) = *(const float4*)(xb + c * NPTS + n0 + mg * 4);
    }
#pragma unroll
    for (int i = 0; i < 4; ++i) {
        int q = tid + i * 256, o = q >> 4, cg = (q & 15) * 4;
        float4 w1v = *(const float4*)(W1 + o * CDIM + cg);
        float4 w2v = *(const float4*)(W2 + o * CDIM + cg);
        *(float4*)(&w1s[o][cg]) = w1v;
        *(float4*)(&wds[o][cg]) = make_float4(w2v.x - w1v.x, w2v.y - w1v.y,
                                              w2v.z - w1v.z, w2v.w - w1v.w);
    }
    if (tid < COUT) bs[tid] = b1[tid] + b2[tid];
    __syncthreads();

    const int tx = tid & 15;
    const int ty = tid >> 4;
    float aA[4][4] = {}, aC[4][4] = {};
#pragma unroll 16
    for (int c = 0; c < CDIM; ++c) {
        float4 xv = *(const float4*)(&xs[c][tx * 4]);
        float xr[4] = { xv.x, xv.y, xv.z, xv.w };
#pragma unroll
        for (int jj = 0; jj < 4; ++jj) {
            float w1e = w1s[ty * 4 + jj][c];
            float wde = wds[ty * 4 + jj][c];
#pragma unroll
            for (int i = 0; i < 4; ++i) {
                aA[i][jj] = fmaf(xr[i], w1e, aA[i][jj]);
                aC[i][jj] = fmaf(xr[i], wde, aC[i][jj]);
            }
        }
    }
#pragma unroll
    for (int i = 0; i < 4; ++i) {
        int n = n0 + tx * 4 + i;
        float* ap = g_A  + ((size_t)b * NPTS + n) * COUT + ty * 4;
        float* cp = g_Cp + ((size_t)b * NPTS + n) * COUT + ty * 4;
        *(float4*)ap = make_float4(aA[i][0], aA[i][1], aA[i][2], aA[i][3]);
        *(float4*)cp = make_float4(aC[i][0] + bs[ty * 4 + 0],
                                   aC[i][1] + bs[ty * 4 + 1],
                                   aC[i][2] + bs[ty * 4 + 2],
                                   aC[i][3] + bs[ty * 4 + 3]);
    }
}

// ---------------- kernel 4: gather-max + relu (2 points/thread ILP) ----------------
__global__ __launch_bounds__(256) void gather_kernel(float* __restrict__ out) {
    const int tid = threadIdx.x;
    const int b   = blockIdx.y;
    const int l   = tid & 63;
    const int g   = tid >> 6;
    const int n1  = blockIdx.x * 128 + l;
    const int n2  = n1 + 64;
    const int* ip1 = g_idx + ((size_t)b * NPTS + n1) * KNBR;
    const int* ip2 = g_idx + ((size_t)b * NPTS + n2) * KNBR;

    float mx1[16], mx2[16];
#pragma unroll
    for (int i = 0; i < 16; ++i) { mx1[i] = -3.4e38f; mx2[i] = -3.4e38f; }

#pragma unroll
    for (int k = 0; k < KNBR; ++k) {
        int j1 = ip1[k], j2 = ip2[k];
        const float4* ap1 = (const float4*)(g_A + ((size_t)b * NPTS + j1) * COUT + g * 16);
        const float4* ap2 = (const float4*)(g_A + ((size_t)b * NPTS + j2) * COUT + g * 16);
#pragma unroll
        for (int q = 0; q < 4; ++q) {
            float4 v1 = ap1[q];
            float4 v2 = ap2[q];
            mx1[q * 4 + 0] = fmaxf(mx1[q * 4 + 0], v1.x);
            mx1[q * 4 + 1] = fmaxf(mx1[q * 4 + 1], v1.y);
            mx1[q * 4 + 2] = fmaxf(mx1[q * 4 + 2], v1.z);
            mx1[q * 4 + 3] = fmaxf(mx1[q * 4 + 3], v1.w);
            mx2[q * 4 + 0] = fmaxf(mx2[q * 4 + 0], v2.x);
            mx2[q * 4 + 1] = fmaxf(mx2[q * 4 + 1], v2.y);
            mx2[q * 4 + 2] = fmaxf(mx2[q * 4 + 2], v2.z);
            mx2[q * 4 + 3] = fmaxf(mx2[q * 4 + 3], v2.w);
        }
    }
    const float4* cp1 = (const float4*)(g_Cp + ((size_t)b * NPTS + n1) * COUT + g * 16);
    const float4* cp2 = (const float4*)(g_Cp + ((size_t)b * NPTS + n2) * COUT + g * 16);
    float* op1 = out + ((size_t)b * COUT + g * 16) * NPTS + n1;
    float* op2 = out + ((size_t)b * COUT + g * 16) * NPTS + n2;
#pragma unroll
    for (int q = 0; q < 4; ++q) {
        float4 c1 = cp1[q];
        float4 c2 = cp2[q];
        op1[(q * 4 + 0) * NPTS] = fmaxf(c1.x + mx1[q * 4 + 0], 0.f);
        op1[(q * 4 + 1) * NPTS] = fmaxf(c1.y + mx1[q * 4 + 1], 0.f);
        op1[(q * 4 + 2) * NPTS] = fmaxf(c1.z + mx1[q * 4 + 2], 0.f);
        op1[(q * 4 + 3) * NPTS] = fmaxf(c1.w + mx1[q * 4 + 3], 0.f);
        op2[(q * 4 + 0) * NPTS] = fmaxf(c2.x + mx2[q * 4 + 0], 0.f);
        op2[(q * 4 + 1) * NPTS] = fmaxf(c2.y + mx2[q * 4 + 1], 0.f);
        op2[(q * 4 + 2) * NPTS] = fmaxf(c2.z + mx2[q * 4 + 2], 0.f);
        op2[(q * 4 + 3) * NPTS] = fmaxf(c2.w + mx2[q * 4 + 3], 0.f);
    }
}

// ---------------- launch ----------------
extern "C" void kernel_launch(void* const* d_in, const int* in_sizes, int n_in,
                              void* d_out, int out_size) {
    const float *x = nullptr, *W1 = nullptr, *b1 = nullptr, *W2 = nullptr, *b2 = nullptr;
    for (int i = 0; i < n_in; ++i) {
        int s = in_sizes[i];
        const float* p = (const float*)d_in[i];
        if      (s == BATCH * CDIM * NPTS) x = p;
        else if (s == COUT * CDIM)        { if (!W1) W1 = p; else W2 = p; }
        else if (s == COUT)               { if (!b1) b1 = p; else b2 = p; }
    }
    float* out = (float*)d_out;
    (void)out_size;

    cudaFuncSetAttribute(knn_mma_kernel, cudaFuncAttributeMaxDynamicSharedMemorySize, KNN_SMEM);

    // knn placed 4th so the fixed ncu capture slot profiles it
    sq_kernel      <<<dim3(NPTS / 256, BATCH), 256>>>(x);
    tr_kernel      <<<dim3(NPTS / 32, CDIM / 32, BATCH), dim3(32, 8)>>>(x);
    feat_kernel    <<<dim3(NPTS / 64, BATCH), 256>>>(x, W1, b1, W2, b2);
    knn_mma_kernel <<<dim3(NPTS / 128, BATCH), 256, KNN_SMEM>>>();
    rescore_kernel <<<dim3(NPTS / 8, BATCH), 256>>>();
    gather_kernel  <<<dim3(NPTS / 128, BATCH), 256>>>(out);
}